// round 2
// baseline (speedup 1.0000x reference)
#include <cuda_runtime.h>
#include <math.h>

// Problem dims (fixed by the reference)
#define B_   2
#define S_   2048
#define D_   1024
#define H_   16
#define DK_  64
#define DFF_ 4096
#define M_   (B_ * S_)   // 4096 tokens

// ---------------------------------------------------------------------------
// Scratch (device globals; allocation inside kernel_launch is forbidden)
// ---------------------------------------------------------------------------
__device__ float g_h   [M_ * D_];    // rmsnorm output (reused for both norms)
__device__ float g_q   [M_ * D_];
__device__ float g_k   [M_ * D_];
__device__ float g_v   [M_ * D_];
__device__ float g_attn[M_ * D_];
__device__ float g_x2  [M_ * D_];    // x + attn @ w_o^T
__device__ float g_u   [M_ * DFF_];
__device__ float g_g   [M_ * DFF_];
__device__ float2 g_rope[S_ * 32];   // (cos, sin) per (pos, freq-pair)

// ---------------------------------------------------------------------------
// RoPE table: double-precision sincos (fast-math-proof, full range reduction)
// ---------------------------------------------------------------------------
__global__ void rope_table_kernel(float2* __restrict__ tab) {
    int idx = blockIdx.x * blockDim.x + threadIdx.x;
    if (idx >= S_ * 32) return;
    int s = idx >> 5;        // position
    int i = idx & 31;        // freq pair index; dk = 2*i
    // inv_freq = 10000^(-2i/64), computed in double
    double invf = exp2(-(double)(2 * i) * (13.287712379549449 / 64.0));
    double ang = (double)s * invf;
    double sd, cd;
    sincos(ang, &sd, &cd);
    tab[idx] = make_float2((float)cd, (float)sd);
}

// ---------------------------------------------------------------------------
// RMSNorm: one block per row (D=1024, 256 threads, float4 each)
// ---------------------------------------------------------------------------
__global__ __launch_bounds__(256) void rmsnorm_kernel(
    const float* __restrict__ x, const float* __restrict__ w,
    float* __restrict__ out) {
    int row = blockIdx.x;
    const float4* xr = (const float4*)(x + (size_t)row * D_);
    int i = threadIdx.x;
    float4 xv = xr[i];
    float ss = xv.x * xv.x + xv.y * xv.y + xv.z * xv.z + xv.w * xv.w;
#pragma unroll
    for (int off = 16; off > 0; off >>= 1)
        ss += __shfl_xor_sync(0xffffffffu, ss, off);
    __shared__ float red[8];
    __shared__ float s_inv;
    if ((threadIdx.x & 31) == 0) red[threadIdx.x >> 5] = ss;
    __syncthreads();
    if (threadIdx.x == 0) {
        float t = 0.f;
#pragma unroll
        for (int j = 0; j < 8; j++) t += red[j];
        s_inv = rsqrtf(t * (1.0f / D_) + 1e-5f);
    }
    __syncthreads();
    float inv = s_inv;
    float4 wv = ((const float4*)w)[i];
    float4 r;
    r.x = inv * xv.x * wv.x;
    r.y = inv * xv.y * wv.y;
    r.z = inv * xv.z * wv.z;
    r.w = inv * xv.w * wv.w;
    ((float4*)(out + (size_t)row * D_))[i] = r;
}

// ---------------------------------------------------------------------------
// SGEMM: C[M,N] = A[M,K] @ B[N,K]^T  (+ optional residual R[M,N])
// 128x128 block tile, BK=16, 256 threads, 8x8 per thread.
// ---------------------------------------------------------------------------
#define BM 128
#define BN 128
#define BK 16
#define TM 8
#define TN 8

__global__ __launch_bounds__(256) void sgemm_kernel(
    const float* __restrict__ A, const float* __restrict__ Bm,
    const float* __restrict__ R, float* __restrict__ C,
    int M, int N, int K) {
    __shared__ float As[BK][BM];
    __shared__ float Bs[BK][BN];

    int tid = threadIdx.x;
    int bm = blockIdx.y * BM;
    int bn = blockIdx.x * BN;

    int lr = tid >> 2;             // 0..63
    int lc = (tid & 3) << 2;       // 0,4,8,12
    int tx = tid & 15, ty = tid >> 4;

    float acc[TM][TN];
#pragma unroll
    for (int i = 0; i < TM; i++)
#pragma unroll
        for (int j = 0; j < TN; j++) acc[i][j] = 0.f;

    const float* Ab = A + (size_t)bm * K;
    const float* Bb = Bm + (size_t)bn * K;

    for (int k0 = 0; k0 < K; k0 += BK) {
#pragma unroll
        for (int i = 0; i < 2; i++) {
            int row = lr + i * 64;
            float4 a = *(const float4*)(Ab + (size_t)row * K + k0 + lc);
            As[lc + 0][row] = a.x; As[lc + 1][row] = a.y;
            As[lc + 2][row] = a.z; As[lc + 3][row] = a.w;
            float4 b = *(const float4*)(Bb + (size_t)row * K + k0 + lc);
            Bs[lc + 0][row] = b.x; Bs[lc + 1][row] = b.y;
            Bs[lc + 2][row] = b.z; Bs[lc + 3][row] = b.w;
        }
        __syncthreads();
#pragma unroll
        for (int k = 0; k < BK; k++) {
            float4 a0 = *(const float4*)&As[k][ty * TM];
            float4 a1 = *(const float4*)&As[k][ty * TM + 4];
            float4 b0 = *(const float4*)&Bs[k][tx * TN];
            float4 b1 = *(const float4*)&Bs[k][tx * TN + 4];
            float av[8] = {a0.x, a0.y, a0.z, a0.w, a1.x, a1.y, a1.z, a1.w};
            float bv[8] = {b0.x, b0.y, b0.z, b0.w, b1.x, b1.y, b1.z, b1.w};
#pragma unroll
            for (int i = 0; i < TM; i++)
#pragma unroll
                for (int j = 0; j < TN; j++) acc[i][j] += av[i] * bv[j];
        }
        __syncthreads();
    }

#pragma unroll
    for (int i = 0; i < TM; i++) {
        int row = bm + ty * TM + i;
        float* Cr = C + (size_t)row * N + bn + tx * TN;
        const float* Rr = R ? (R + (size_t)row * N + bn + tx * TN) : nullptr;
#pragma unroll
        for (int j = 0; j < TN; j += 4) {
            float4 v;
            v.x = acc[i][j]; v.y = acc[i][j + 1];
            v.z = acc[i][j + 2]; v.w = acc[i][j + 3];
            if (Rr) {
                float4 r = *(const float4*)(Rr + j);
                v.x += r.x; v.y += r.y; v.z += r.z; v.w += r.w;
            }
            *(float4*)(Cr + j) = v;
        }
    }
}

// ---------------------------------------------------------------------------
// RoPE apply: in-place on q and k, reading precomputed (cos,sin) table.
// Layout [m, e], e = h*64 + dk, pos = m % S, pair index i = (dk_even)/2.
// ---------------------------------------------------------------------------
__global__ void rope_kernel(float* __restrict__ q, float* __restrict__ k,
                            const float2* __restrict__ tab) {
    int idx = blockIdx.x * blockDim.x + threadIdx.x;
    if (idx >= M_ * D_ / 2) return;
    int e = idx * 2;
    int m = e >> 10;            // / D_
    int d = e & (D_ - 1);
    int s = m & (S_ - 1);       // position within sequence
    int i = (d & (DK_ - 1)) >> 1;
    float2 cs = tab[(s << 5) + i];
    float c = cs.x, sn = cs.y;
    size_t p = (size_t)m * D_ + d;
    float qe = q[p], qo = q[p + 1];
    q[p]     = c * qe - sn * qo;
    q[p + 1] = sn * qe + c * qo;
    float ke = k[p], ko = k[p + 1];
    k[p]     = c * ke - sn * ko;
    k[p + 1] = sn * ke + c * ko;
}

// ---------------------------------------------------------------------------
// Causal flash attention (fp32, online softmax).
// Grid: (S/128, H, B), 128 threads. Each thread owns one query row.
// ---------------------------------------------------------------------------
#define KVT 64
__global__ __launch_bounds__(128) void attn_kernel(
    const float* __restrict__ Q, const float* __restrict__ Kg,
    const float* __restrict__ Vg, float* __restrict__ O) {
    __shared__ float Ks[KVT][DK_ + 4];
    __shared__ float Vs[KVT][DK_ + 4];

    int tid = threadIdx.x;
    int qt = blockIdx.x, h = blockIdx.y, b = blockIdx.z;
    int s_q = qt * 128 + tid;

    const float* qp = Q + (((size_t)(b * S_ + s_q)) * H_ + h) * DK_;
    float q[DK_];
#pragma unroll
    for (int d = 0; d < DK_; d += 4) {
        float4 t = *(const float4*)(qp + d);
        q[d] = t.x; q[d + 1] = t.y; q[d + 2] = t.z; q[d + 3] = t.w;
    }
    float o[DK_];
#pragma unroll
    for (int d = 0; d < DK_; d++) o[d] = 0.f;
    float mval = -INFINITY, l = 0.f;

    int ntiles = qt * 2 + 2;
    for (int t = 0; t < ntiles; t++) {
        int r = tid >> 1, c0 = (tid & 1) * 32;
        const float* kp = Kg + (((size_t)(b * S_ + t * KVT + r)) * H_ + h) * DK_ + c0;
        const float* vp = Vg + (((size_t)(b * S_ + t * KVT + r)) * H_ + h) * DK_ + c0;
        __syncthreads();
#pragma unroll
        for (int c = 0; c < 32; c += 4) {
            *(float4*)&Ks[r][c0 + c] = *(const float4*)(kp + c);
            *(float4*)&Vs[r][c0 + c] = *(const float4*)(vp + c);
        }
        __syncthreads();

#pragma unroll 1
        for (int j0 = 0; j0 < KVT; j0 += 16) {
            float sreg[16];
            float cmax = -INFINITY;
#pragma unroll
            for (int jj = 0; jj < 16; jj++) {
                float sum = 0.f;
#pragma unroll
                for (int d = 0; d < DK_; d += 4) {
                    float4 kk = *(const float4*)&Ks[j0 + jj][d];
                    sum += q[d] * kk.x + q[d + 1] * kk.y
                         + q[d + 2] * kk.z + q[d + 3] * kk.w;
                }
                sum *= 0.125f;  // 1/sqrt(64)
                int kv = t * KVT + j0 + jj;
                if (kv > s_q) sum = -INFINITY;
                sreg[jj] = sum;
                cmax = fmaxf(cmax, sum);
            }
            float mnew = fmaxf(mval, cmax);
            if (mnew == -INFINITY) continue;
            float corr = expf(mval - mnew);
            l *= corr;
#pragma unroll
            for (int d = 0; d < DK_; d++) o[d] *= corr;
#pragma unroll
            for (int jj = 0; jj < 16; jj++) {
                float p = expf(sreg[jj] - mnew);
                l += p;
#pragma unroll
                for (int d = 0; d < DK_; d += 4) {
                    float4 vv = *(const float4*)&Vs[j0 + jj][d];
                    o[d]     += p * vv.x;
                    o[d + 1] += p * vv.y;
                    o[d + 2] += p * vv.z;
                    o[d + 3] += p * vv.w;
                }
            }
            mval = mnew;
        }
    }

    float invl = 1.f / l;
    float* op = O + (((size_t)(b * S_ + s_q)) * H_ + h) * DK_;
#pragma unroll
    for (int d = 0; d < DK_; d += 4) {
        float4 t;
        t.x = o[d] * invl; t.y = o[d + 1] * invl;
        t.z = o[d + 2] * invl; t.w = o[d + 3] * invl;
        *(float4*)(op + d) = t;
    }
}

// ---------------------------------------------------------------------------
// SwiGLU: u <- u * sigmoid(u) * g   (elementwise, float4)
// ---------------------------------------------------------------------------
__global__ void swiglu_kernel(float* __restrict__ u, const float* __restrict__ g, int n4) {
    int i = blockIdx.x * blockDim.x + threadIdx.x;
    if (i >= n4) return;
    float4 uv = ((const float4*)u)[i];
    float4 gv = ((const float4*)g)[i];
    float4 r;
    r.x = uv.x * (1.0f / (1.0f + expf(-uv.x))) * gv.x;
    r.y = uv.y * (1.0f / (1.0f + expf(-uv.y))) * gv.y;
    r.z = uv.z * (1.0f / (1.0f + expf(-uv.z))) * gv.z;
    r.w = uv.w * (1.0f / (1.0f + expf(-uv.w))) * gv.w;
    ((float4*)u)[i] = r;
}

// ---------------------------------------------------------------------------
// Launch
// ---------------------------------------------------------------------------
extern "C" void kernel_launch(void* const* d_in, const int* in_sizes, int n_in,
                              void* d_out, int out_size) {
    const float* x   = (const float*)d_in[0];
    const float* w_q = (const float*)d_in[1];
    const float* w_k = (const float*)d_in[2];
    const float* w_v = (const float*)d_in[3];
    const float* w_o = (const float*)d_in[4];
    const float* ln1 = (const float*)d_in[5];
    const float* ln2 = (const float*)d_in[6];
    const float* w1  = (const float*)d_in[7];
    const float* w2  = (const float*)d_in[8];
    const float* w3  = (const float*)d_in[9];
    float* out = (float*)d_out;

    float *h, *q, *k, *v, *attn, *x2, *u, *gp;
    float2* rope;
    cudaGetSymbolAddress((void**)&h,    g_h);
    cudaGetSymbolAddress((void**)&q,    g_q);
    cudaGetSymbolAddress((void**)&k,    g_k);
    cudaGetSymbolAddress((void**)&v,    g_v);
    cudaGetSymbolAddress((void**)&attn, g_attn);
    cudaGetSymbolAddress((void**)&x2,   g_x2);
    cudaGetSymbolAddress((void**)&u,    g_u);
    cudaGetSymbolAddress((void**)&gp,   g_g);
    cudaGetSymbolAddress((void**)&rope, g_rope);

    // 0) RoPE cos/sin table (double-precision sincos; fast-math-proof)
    rope_table_kernel<<<(S_ * 32 + 255) / 256, 256>>>(rope);

    // 1) h = rmsnorm(x, ln1)
    rmsnorm_kernel<<<M_, 256>>>(x, ln1, h);

    // 2) q/k/v = h @ w^T
    dim3 gProj(D_ / BN, M_ / BM);
    sgemm_kernel<<<gProj, 256>>>(h, w_q, nullptr, q, M_, D_, D_);
    sgemm_kernel<<<gProj, 256>>>(h, w_k, nullptr, k, M_, D_, D_);
    sgemm_kernel<<<gProj, 256>>>(h, w_v, nullptr, v, M_, D_, D_);

    // 3) RoPE on q, k
    rope_kernel<<<(M_ * D_ / 2 + 255) / 256, 256>>>(q, k, rope);

    // 4) causal attention
    attn_kernel<<<dim3(S_ / 128, H_, B_), 128>>>(q, k, v, attn);

    // 5) x2 = x + attn @ w_o^T
    sgemm_kernel<<<gProj, 256>>>(attn, w_o, x, x2, M_, D_, D_);

    // 6) h = rmsnorm(x2, ln2)
    rmsnorm_kernel<<<M_, 256>>>(x2, ln2, h);

    // 7) u = h @ w1^T ; g = h @ w3^T
    dim3 gFF(DFF_ / BN, M_ / BM);
    sgemm_kernel<<<gFF, 256>>>(h, w1, nullptr, u,  M_, DFF_, D_);
    sgemm_kernel<<<gFF, 256>>>(h, w3, nullptr, gp, M_, DFF_, D_);

    // 8) u = u * sigmoid(u) * g
    swiglu_kernel<<<(M_ * DFF_ / 4 + 255) / 256, 256>>>(u, gp, M_ * DFF_ / 4);

    // 9) out = x2 + u @ w2^T
    sgemm_kernel<<<gProj, 256>>>(u, w2, x2, out, M_, D_, DFF_);
}

// round 5
// speedup vs baseline: 2.0314x; 2.0314x over previous
#include <cuda_runtime.h>
#include <cuda_bf16.h>
#include <math.h>
#include <stdint.h>

// Problem dims (fixed by the reference)
#define B_   2
#define S_   2048
#define D_   1024
#define H_   16
#define DK_  64
#define DFF_ 4096
#define M_   (B_ * S_)   // 4096 tokens

// ---------------------------------------------------------------------------
// Scratch (device globals; allocation inside kernel_launch is forbidden)
// ---------------------------------------------------------------------------
__device__ float g_h   [M_ * D_];
__device__ float g_q   [M_ * D_];
__device__ float g_k   [M_ * D_];
__device__ float g_v   [M_ * D_];
__device__ float g_attn[M_ * D_];
__device__ float g_x2  [M_ * D_];
__device__ float g_u   [M_ * DFF_];
__device__ float g_g   [M_ * DFF_];
__device__ float2 g_rope[S_ * 32];

// bf16 split buffers. NOTE: activations must hold M_*DFF_ = 16M elements
// (the SwiGLU output feeding the final GEMM) — undersizing this corrupted
// adjacent weight buffers in R4.
#define ASZ (16u * 1048576u)
#define WSZ (16u * 1048576u)
__device__ __nv_bfloat16 g_sh[ASZ];
__device__ __nv_bfloat16 g_sl[ASZ];
__device__ __nv_bfloat16 g_wh[WSZ];
__device__ __nv_bfloat16 g_wl[WSZ];

// weight offsets (elements)
#define OW_Q  0u
#define OW_K  1048576u
#define OW_V  2097152u
#define OW_O  3145728u
#define OW_1  4194304u
#define OW_3  8388608u
#define OW_2  12582912u

// ---------------------------------------------------------------------------
// fp32 -> bf16 hi/lo split (error-compensated GEMM inputs)
// ---------------------------------------------------------------------------
__global__ void split_kernel(const float* __restrict__ s,
                             __nv_bfloat16* __restrict__ hi,
                             __nv_bfloat16* __restrict__ lo, int n4) {
    int i = blockIdx.x * blockDim.x + threadIdx.x;
    if (i >= n4) return;
    float4 v = ((const float4*)s)[i];
    __nv_bfloat16 h0 = __float2bfloat16(v.x);
    __nv_bfloat16 h1 = __float2bfloat16(v.y);
    __nv_bfloat16 h2 = __float2bfloat16(v.z);
    __nv_bfloat16 h3 = __float2bfloat16(v.w);
    __nv_bfloat16 l0 = __float2bfloat16(v.x - __bfloat162float(h0));
    __nv_bfloat16 l1 = __float2bfloat16(v.y - __bfloat162float(h1));
    __nv_bfloat16 l2 = __float2bfloat16(v.z - __bfloat162float(h2));
    __nv_bfloat16 l3 = __float2bfloat16(v.w - __bfloat162float(h3));
    uint2 uh, ul;
    uh.x = (uint32_t)__bfloat16_as_ushort(h0) | ((uint32_t)__bfloat16_as_ushort(h1) << 16);
    uh.y = (uint32_t)__bfloat16_as_ushort(h2) | ((uint32_t)__bfloat16_as_ushort(h3) << 16);
    ul.x = (uint32_t)__bfloat16_as_ushort(l0) | ((uint32_t)__bfloat16_as_ushort(l1) << 16);
    ul.y = (uint32_t)__bfloat16_as_ushort(l2) | ((uint32_t)__bfloat16_as_ushort(l3) << 16);
    ((uint2*)hi)[i] = uh;
    ((uint2*)lo)[i] = ul;
}

// ---------------------------------------------------------------------------
// HMMA helpers (base PTX, legal at compute_103)
// ---------------------------------------------------------------------------
__device__ __forceinline__ uint32_t smem_u32(const void* p) {
    uint32_t a;
    asm("{ .reg .u64 t; cvta.to.shared.u64 t, %1; cvt.u32.u64 %0, t; }"
        : "=r"(a) : "l"(p));
    return a;
}
__device__ __forceinline__ void cp16(uint32_t dst, const void* src) {
    asm volatile("cp.async.cg.shared.global [%0], [%1], 16;"
                 :: "r"(dst), "l"(src));
}
__device__ __forceinline__ void ldm4(uint32_t* r, uint32_t a) {
    asm volatile("ldmatrix.sync.aligned.m8n8.x4.shared.b16 {%0,%1,%2,%3}, [%4];"
                 : "=r"(r[0]), "=r"(r[1]), "=r"(r[2]), "=r"(r[3]) : "r"(a));
}
__device__ __forceinline__ void mma16816(float* c, const uint32_t* a,
                                         uint32_t b0, uint32_t b1) {
    asm volatile(
        "mma.sync.aligned.m16n8k16.row.col.f32.bf16.bf16.f32 "
        "{%0,%1,%2,%3}, {%4,%5,%6,%7}, {%8,%9}, {%0,%1,%2,%3};"
        : "+f"(c[0]), "+f"(c[1]), "+f"(c[2]), "+f"(c[3])
        : "r"(a[0]), "r"(a[1]), "r"(a[2]), "r"(a[3]), "r"(b0), "r"(b1));
}

// ---------------------------------------------------------------------------
// bf16-split GEMM via mma.sync: C[M,N] = A[M,K] @ B[N,K]^T (+R)
// 128x128 CTA tile, BK=32, 8 warps x (32x64), cp.async double buffer.
// Smem stage: Ah,Al,Bh,Bl each 128 rows x 32 halves @ pitch 40 halves (80B).
// ---------------------------------------------------------------------------
#define LDSP    80            // bytes per smem row
#define ARRSZ   10240         // 128 * 80
#define STAGE   40960         // 4 arrays
#define MG_SMEM (2 * STAGE)

__global__ __launch_bounds__(256, 2) void mma_gemm_kernel(
    const __nv_bfloat16* __restrict__ Ah, const __nv_bfloat16* __restrict__ Al,
    const __nv_bfloat16* __restrict__ Bh, const __nv_bfloat16* __restrict__ Bl,
    const float* __restrict__ R, float* __restrict__ C,
    int M, int N, int K) {
    extern __shared__ char smx[];
    uint32_t sb = smem_u32(smx);
    int tid = threadIdx.x, wid = tid >> 5, lane = tid & 31;
    int bm = blockIdx.y * 128, bn = blockIdx.x * 128;
    int wm = (wid & 3) * 32, wn = (wid >> 2) * 64;

    const __nv_bfloat16* pAh = Ah + (size_t)bm * K;
    const __nv_bfloat16* pAl = Al + (size_t)bm * K;
    const __nv_bfloat16* pBh = Bh + (size_t)bn * K;
    const __nv_bfloat16* pBl = Bl + (size_t)bn * K;

    float acc[2][8][4];
#pragma unroll
    for (int i = 0; i < 2; i++)
#pragma unroll
        for (int j = 0; j < 8; j++)
#pragma unroll
            for (int t = 0; t < 4; t++) acc[i][j][t] = 0.f;

    int nch = K >> 5;

    // per-thread load geometry (8 x cp16 per chunk)
    int jrow0 = tid >> 2;            // sub 0: rows 0..63
    int jrow1 = 64 + (tid >> 2);     // sub 1: rows 64..127
    int kb = (tid & 3);              // 16B column within 64B row

#define LOADCHUNK(c, s)                                                        \
    {                                                                          \
        int k0 = (c) << 5;                                                     \
        uint32_t stg = sb + (s) * STAGE;                                       \
        {                                                                      \
            uint32_t db = stg + jrow0 * LDSP + kb * 16;                        \
            size_t go = (size_t)jrow0 * K + k0 + kb * 8;                       \
            cp16(db, pAh + go);                                                \
            cp16(db + ARRSZ, pAl + go);                                        \
            cp16(db + 2 * ARRSZ, pBh + go);                                    \
            cp16(db + 3 * ARRSZ, pBl + go);                                    \
        }                                                                      \
        {                                                                      \
            uint32_t db = stg + jrow1 * LDSP + kb * 16;                        \
            size_t go = (size_t)jrow1 * K + k0 + kb * 8;                       \
            cp16(db, pAh + go);                                                \
            cp16(db + ARRSZ, pAl + go);                                        \
            cp16(db + 2 * ARRSZ, pBh + go);                                    \
            cp16(db + 3 * ARRSZ, pBl + go);                                    \
        }                                                                      \
        asm volatile("cp.async.commit_group;");                                \
    }

    LOADCHUNK(0, 0)

    for (int c = 0; c < nch; c++) {
        int s = c & 1;
        if (c + 1 < nch) {
            LOADCHUNK(c + 1, s ^ 1)
            asm volatile("cp.async.wait_group 1;");
        } else {
            asm volatile("cp.async.wait_group 0;");
        }
        __syncthreads();

        uint32_t stg = sb + s * STAGE;
#pragma unroll
        for (int ks = 0; ks < 2; ks++) {
            uint32_t ar = stg + (wm + (lane & 15)) * LDSP
                        + (ks * 16 + (lane >> 4) * 8) * 2;
            uint32_t ahf[2][4], alf[2][4];
            ldm4(ahf[0], ar);
            ldm4(ahf[1], ar + 16 * LDSP);
            ldm4(alf[0], ar + ARRSZ);
            ldm4(alf[1], ar + ARRSZ + 16 * LDSP);
            uint32_t br = stg + 2 * ARRSZ
                        + (wn + (lane & 7) + ((lane >> 4) & 1) * 8) * LDSP
                        + (ks * 16 + ((lane >> 3) & 1) * 8) * 2;
#pragma unroll
            for (int pass = 0; pass < 3; pass++) {
                uint32_t boff = (pass == 1) ? ARRSZ : 0u;
#pragma unroll
                for (int g = 0; g < 4; g++) {
                    uint32_t b[4];
                    ldm4(b, br + boff + g * 16 * LDSP);
                    if (pass == 2) {
                        mma16816(acc[0][2 * g],     alf[0], b[0], b[1]);
                        mma16816(acc[0][2 * g + 1], alf[0], b[2], b[3]);
                        mma16816(acc[1][2 * g],     alf[1], b[0], b[1]);
                        mma16816(acc[1][2 * g + 1], alf[1], b[2], b[3]);
                    } else {
                        mma16816(acc[0][2 * g],     ahf[0], b[0], b[1]);
                        mma16816(acc[0][2 * g + 1], ahf[0], b[2], b[3]);
                        mma16816(acc[1][2 * g],     ahf[1], b[0], b[1]);
                        mma16816(acc[1][2 * g + 1], ahf[1], b[2], b[3]);
                    }
                }
            }
        }
        __syncthreads();
    }

    // epilogue: c[m][n] layout m = lane/4 (+8), n = (lane%4)*2 (+1)
#pragma unroll
    for (int mt = 0; mt < 2; mt++) {
        int m0 = bm + wm + mt * 16 + (lane >> 2);
#pragma unroll
        for (int nt = 0; nt < 8; nt++) {
            int n0 = bn + wn + nt * 8 + (lane & 3) * 2;
            float2 v0 = make_float2(acc[mt][nt][0], acc[mt][nt][1]);
            float2 v1 = make_float2(acc[mt][nt][2], acc[mt][nt][3]);
            if (R) {
                float2 r0 = *(const float2*)(R + (size_t)m0 * N + n0);
                float2 r1 = *(const float2*)(R + (size_t)(m0 + 8) * N + n0);
                v0.x += r0.x; v0.y += r0.y;
                v1.x += r1.x; v1.y += r1.y;
            }
            *(float2*)(C + (size_t)m0 * N + n0) = v0;
            *(float2*)(C + (size_t)(m0 + 8) * N + n0) = v1;
        }
    }
}

// ---------------------------------------------------------------------------
// RoPE table: double-precision sincos (fast-math-proof, full range reduction)
// ---------------------------------------------------------------------------
__global__ void rope_table_kernel(float2* __restrict__ tab) {
    int idx = blockIdx.x * blockDim.x + threadIdx.x;
    if (idx >= S_ * 32) return;
    int s = idx >> 5;
    int i = idx & 31;
    double invf = exp2(-(double)(2 * i) * (13.287712379549449 / 64.0));
    double ang = (double)s * invf;
    double sd, cd;
    sincos(ang, &sd, &cd);
    tab[idx] = make_float2((float)cd, (float)sd);
}

// ---------------------------------------------------------------------------
// RMSNorm
// ---------------------------------------------------------------------------
__global__ __launch_bounds__(256) void rmsnorm_kernel(
    const float* __restrict__ x, const float* __restrict__ w,
    float* __restrict__ out) {
    int row = blockIdx.x;
    const float4* xr = (const float4*)(x + (size_t)row * D_);
    int i = threadIdx.x;
    float4 xv = xr[i];
    float ss = xv.x * xv.x + xv.y * xv.y + xv.z * xv.z + xv.w * xv.w;
#pragma unroll
    for (int off = 16; off > 0; off >>= 1)
        ss += __shfl_xor_sync(0xffffffffu, ss, off);
    __shared__ float red[8];
    __shared__ float s_inv;
    if ((threadIdx.x & 31) == 0) red[threadIdx.x >> 5] = ss;
    __syncthreads();
    if (threadIdx.x == 0) {
        float t = 0.f;
#pragma unroll
        for (int j = 0; j < 8; j++) t += red[j];
        s_inv = rsqrtf(t * (1.0f / D_) + 1e-5f);
    }
    __syncthreads();
    float inv = s_inv;
    float4 wv = ((const float4*)w)[i];
    float4 r;
    r.x = inv * xv.x * wv.x;
    r.y = inv * xv.y * wv.y;
    r.z = inv * xv.z * wv.z;
    r.w = inv * xv.w * wv.w;
    ((float4*)(out + (size_t)row * D_))[i] = r;
}

// ---------------------------------------------------------------------------
// RoPE apply (table-driven)
// ---------------------------------------------------------------------------
__global__ void rope_kernel(float* __restrict__ q, float* __restrict__ k,
                            const float2* __restrict__ tab) {
    int idx = blockIdx.x * blockDim.x + threadIdx.x;
    if (idx >= M_ * D_ / 2) return;
    int e = idx * 2;
    int m = e >> 10;
    int d = e & (D_ - 1);
    int s = m & (S_ - 1);
    int i = (d & (DK_ - 1)) >> 1;
    float2 cs = tab[(s << 5) + i];
    float c = cs.x, sn = cs.y;
    size_t p = (size_t)m * D_ + d;
    float qe = q[p], qo = q[p + 1];
    q[p]     = c * qe - sn * qo;
    q[p + 1] = sn * qe + c * qo;
    float ke = k[p], ko = k[p + 1];
    k[p]     = c * ke - sn * ko;
    k[p + 1] = sn * ke + c * ko;
}

// ---------------------------------------------------------------------------
// Causal flash attention (fp32, online softmax)
// ---------------------------------------------------------------------------
#define KVT 64
__global__ __launch_bounds__(128) void attn_kernel(
    const float* __restrict__ Q, const float* __restrict__ Kg,
    const float* __restrict__ Vg, float* __restrict__ O) {
    __shared__ float Ks[KVT][DK_ + 4];
    __shared__ float Vs[KVT][DK_ + 4];

    int tid = threadIdx.x;
    int qt = blockIdx.x, h = blockIdx.y, b = blockIdx.z;
    int s_q = qt * 128 + tid;

    const float* qp = Q + (((size_t)(b * S_ + s_q)) * H_ + h) * DK_;
    float q[DK_];
#pragma unroll
    for (int d = 0; d < DK_; d += 4) {
        float4 t = *(const float4*)(qp + d);
        q[d] = t.x; q[d + 1] = t.y; q[d + 2] = t.z; q[d + 3] = t.w;
    }
    float o[DK_];
#pragma unroll
    for (int d = 0; d < DK_; d++) o[d] = 0.f;
    float mval = -INFINITY, l = 0.f;

    int ntiles = qt * 2 + 2;
    for (int t = 0; t < ntiles; t++) {
        int r = tid >> 1, c0 = (tid & 1) * 32;
        const float* kp = Kg + (((size_t)(b * S_ + t * KVT + r)) * H_ + h) * DK_ + c0;
        const float* vp = Vg + (((size_t)(b * S_ + t * KVT + r)) * H_ + h) * DK_ + c0;
        __syncthreads();
#pragma unroll
        for (int c = 0; c < 32; c += 4) {
            *(float4*)&Ks[r][c0 + c] = *(const float4*)(kp + c);
            *(float4*)&Vs[r][c0 + c] = *(const float4*)(vp + c);
        }
        __syncthreads();

#pragma unroll 1
        for (int j0 = 0; j0 < KVT; j0 += 16) {
            float sreg[16];
            float cmax = -INFINITY;
#pragma unroll
            for (int jj = 0; jj < 16; jj++) {
                float sum = 0.f;
#pragma unroll
                for (int d = 0; d < DK_; d += 4) {
                    float4 kk = *(const float4*)&Ks[j0 + jj][d];
                    sum += q[d] * kk.x + q[d + 1] * kk.y
                         + q[d + 2] * kk.z + q[d + 3] * kk.w;
                }
                sum *= 0.125f;
                int kv = t * KVT + j0 + jj;
                if (kv > s_q) sum = -INFINITY;
                sreg[jj] = sum;
                cmax = fmaxf(cmax, sum);
            }
            float mnew = fmaxf(mval, cmax);
            if (mnew == -INFINITY) continue;
            float corr = expf(mval - mnew);
            l *= corr;
#pragma unroll
            for (int d = 0; d < DK_; d++) o[d] *= corr;
#pragma unroll
            for (int jj = 0; jj < 16; jj++) {
                float p = expf(sreg[jj] - mnew);
                l += p;
#pragma unroll
                for (int d = 0; d < DK_; d += 4) {
                    float4 vv = *(const float4*)&Vs[j0 + jj][d];
                    o[d]     += p * vv.x;
                    o[d + 1] += p * vv.y;
                    o[d + 2] += p * vv.z;
                    o[d + 3] += p * vv.w;
                }
            }
            mval = mnew;
        }
    }

    float invl = 1.f / l;
    float* op = O + (((size_t)(b * S_ + s_q)) * H_ + h) * DK_;
#pragma unroll
    for (int d = 0; d < DK_; d += 4) {
        float4 t;
        t.x = o[d] * invl; t.y = o[d + 1] * invl;
        t.z = o[d + 2] * invl; t.w = o[d + 3] * invl;
        *(float4*)(op + d) = t;
    }
}

// ---------------------------------------------------------------------------
// SwiGLU
// ---------------------------------------------------------------------------
__global__ void swiglu_kernel(float* __restrict__ u, const float* __restrict__ g, int n4) {
    int i = blockIdx.x * blockDim.x + threadIdx.x;
    if (i >= n4) return;
    float4 uv = ((const float4*)u)[i];
    float4 gv = ((const float4*)g)[i];
    float4 r;
    r.x = uv.x * (1.0f / (1.0f + expf(-uv.x))) * gv.x;
    r.y = uv.y * (1.0f / (1.0f + expf(-uv.y))) * gv.y;
    r.z = uv.z * (1.0f / (1.0f + expf(-uv.z))) * gv.z;
    r.w = uv.w * (1.0f / (1.0f + expf(-uv.w))) * gv.w;
    ((float4*)u)[i] = r;
}

// ---------------------------------------------------------------------------
// Launch
// ---------------------------------------------------------------------------
extern "C" void kernel_launch(void* const* d_in, const int* in_sizes, int n_in,
                              void* d_out, int out_size) {
    const float* x   = (const float*)d_in[0];
    const float* w_q = (const float*)d_in[1];
    const float* w_k = (const float*)d_in[2];
    const float* w_v = (const float*)d_in[3];
    const float* w_o = (const float*)d_in[4];
    const float* ln1 = (const float*)d_in[5];
    const float* ln2 = (const float*)d_in[6];
    const float* w1  = (const float*)d_in[7];
    const float* w2  = (const float*)d_in[8];
    const float* w3  = (const float*)d_in[9];
    float* out = (float*)d_out;

    float *h, *q, *k, *v, *attn, *x2, *u, *gp;
    float2* rope;
    __nv_bfloat16 *sh, *sl, *wh, *wl;
    cudaGetSymbolAddress((void**)&h,    g_h);
    cudaGetSymbolAddress((void**)&q,    g_q);
    cudaGetSymbolAddress((void**)&k,    g_k);
    cudaGetSymbolAddress((void**)&v,    g_v);
    cudaGetSymbolAddress((void**)&attn, g_attn);
    cudaGetSymbolAddress((void**)&x2,   g_x2);
    cudaGetSymbolAddress((void**)&u,    g_u);
    cudaGetSymbolAddress((void**)&gp,   g_g);
    cudaGetSymbolAddress((void**)&rope, g_rope);
    cudaGetSymbolAddress((void**)&sh,   g_sh);
    cudaGetSymbolAddress((void**)&sl,   g_sl);
    cudaGetSymbolAddress((void**)&wh,   g_wh);
    cudaGetSymbolAddress((void**)&wl,   g_wl);

    cudaFuncSetAttribute(mma_gemm_kernel,
                         cudaFuncAttributeMaxDynamicSharedMemorySize, MG_SMEM);

    // 0) RoPE table + weight splits
    rope_table_kernel<<<(S_ * 32 + 255) / 256, 256>>>(rope);
    split_kernel<<<1024, 256>>>(w_q, wh + OW_Q, wl + OW_Q, 262144);
    split_kernel<<<1024, 256>>>(w_k, wh + OW_K, wl + OW_K, 262144);
    split_kernel<<<1024, 256>>>(w_v, wh + OW_V, wl + OW_V, 262144);
    split_kernel<<<1024, 256>>>(w_o, wh + OW_O, wl + OW_O, 262144);
    split_kernel<<<4096, 256>>>(w1,  wh + OW_1, wl + OW_1, 1048576);
    split_kernel<<<4096, 256>>>(w3,  wh + OW_3, wl + OW_3, 1048576);
    split_kernel<<<4096, 256>>>(w2,  wh + OW_2, wl + OW_2, 1048576);

    // 1) h = rmsnorm(x, ln1); split
    rmsnorm_kernel<<<M_, 256>>>(x, ln1, h);
    split_kernel<<<4096, 256>>>(h, sh, sl, 1048576);

    // 2) q/k/v = h @ w^T  (HMMA split GEMM)
    dim3 gProj(D_ / 128, M_ / 128);
    mma_gemm_kernel<<<gProj, 256, MG_SMEM>>>(sh, sl, wh + OW_Q, wl + OW_Q, nullptr, q, M_, D_, D_);
    mma_gemm_kernel<<<gProj, 256, MG_SMEM>>>(sh, sl, wh + OW_K, wl + OW_K, nullptr, k, M_, D_, D_);
    mma_gemm_kernel<<<gProj, 256, MG_SMEM>>>(sh, sl, wh + OW_V, wl + OW_V, nullptr, v, M_, D_, D_);

    // 3) RoPE on q, k
    rope_kernel<<<(M_ * D_ / 2 + 255) / 256, 256>>>(q, k, rope);

    // 4) causal attention (fp32)
    attn_kernel<<<dim3(S_ / 128, H_, B_), 128>>>(q, k, v, attn);

    // 5) x2 = x + attn @ w_o^T
    split_kernel<<<4096, 256>>>(attn, sh, sl, 1048576);
    mma_gemm_kernel<<<gProj, 256, MG_SMEM>>>(sh, sl, wh + OW_O, wl + OW_O, x, x2, M_, D_, D_);

    // 6) h = rmsnorm(x2, ln2); split
    rmsnorm_kernel<<<M_, 256>>>(x2, ln2, h);
    split_kernel<<<4096, 256>>>(h, sh, sl, 1048576);

    // 7) u = h @ w1^T ; g = h @ w3^T
    dim3 gFF(DFF_ / 128, M_ / 128);
    mma_gemm_kernel<<<gFF, 256, MG_SMEM>>>(sh, sl, wh + OW_1, wl + OW_1, nullptr, u,  M_, DFF_, D_);
    mma_gemm_kernel<<<gFF, 256, MG_SMEM>>>(sh, sl, wh + OW_3, wl + OW_3, nullptr, gp, M_, DFF_, D_);

    // 8) u = u * sigmoid(u) * g ; split (16M elements -> needs ASZ-sized buffers)
    swiglu_kernel<<<(M_ * DFF_ / 4 + 255) / 256, 256>>>(u, gp, M_ * DFF_ / 4);
    split_kernel<<<16384, 256>>>(u, sh, sl, 4194304);

    // 9) out = x2 + u @ w2^T  (K = 4096)
    mma_gemm_kernel<<<gProj, 256, MG_SMEM>>>(sh, sl, wh + OW_2, wl + OW_2, x2, out, M_, D_, DFF_);
}

// round 6
// speedup vs baseline: 3.3657x; 1.6569x over previous
#include <cuda_runtime.h>
#include <cuda_bf16.h>
#include <math.h>
#include <stdint.h>

// Problem dims (fixed by the reference)
#define B_   2
#define S_   2048
#define D_   1024
#define H_   16
#define DK_  64
#define DFF_ 4096
#define M_   (B_ * S_)   // 4096 tokens

// ---------------------------------------------------------------------------
// Scratch (device globals; allocation inside kernel_launch is forbidden)
// ---------------------------------------------------------------------------
__device__ float g_h   [M_ * D_];
__device__ float g_q   [M_ * D_];
__device__ float g_k   [M_ * D_];
__device__ float g_v   [M_ * D_];
__device__ float g_attn[M_ * D_];
__device__ float g_x2  [M_ * D_];
__device__ float g_u   [M_ * DFF_];
__device__ float g_g   [M_ * DFF_];
__device__ float2 g_rope[S_ * 32];

// bf16 split buffers (activations must hold M_*DFF_ = 16M elements).
// During attention, g_sh/g_sl hold roped q/k/v splits at offsets 0/4M/8M.
#define ASZ (16u * 1048576u)
#define WSZ (16u * 1048576u)
__device__ __nv_bfloat16 g_sh[ASZ];
__device__ __nv_bfloat16 g_sl[ASZ];
__device__ __nv_bfloat16 g_wh[WSZ];
__device__ __nv_bfloat16 g_wl[WSZ];

// offsets (elements)
#define OW_Q  0u
#define OW_K  1048576u
#define OW_V  2097152u
#define OW_O  3145728u
#define OW_1  4194304u
#define OW_3  8388608u
#define OW_2  12582912u
#define OQ_   0u
#define OK_   4194304u
#define OV_   8388608u

// ---------------------------------------------------------------------------
// fp32 -> bf16 hi/lo split
// ---------------------------------------------------------------------------
__global__ void split_kernel(const float* __restrict__ s,
                             __nv_bfloat16* __restrict__ hi,
                             __nv_bfloat16* __restrict__ lo, int n4) {
    int i = blockIdx.x * blockDim.x + threadIdx.x;
    if (i >= n4) return;
    float4 v = ((const float4*)s)[i];
    __nv_bfloat16 h0 = __float2bfloat16(v.x);
    __nv_bfloat16 h1 = __float2bfloat16(v.y);
    __nv_bfloat16 h2 = __float2bfloat16(v.z);
    __nv_bfloat16 h3 = __float2bfloat16(v.w);
    __nv_bfloat16 l0 = __float2bfloat16(v.x - __bfloat162float(h0));
    __nv_bfloat16 l1 = __float2bfloat16(v.y - __bfloat162float(h1));
    __nv_bfloat16 l2 = __float2bfloat16(v.z - __bfloat162float(h2));
    __nv_bfloat16 l3 = __float2bfloat16(v.w - __bfloat162float(h3));
    uint2 uh, ul;
    uh.x = (uint32_t)__bfloat16_as_ushort(h0) | ((uint32_t)__bfloat16_as_ushort(h1) << 16);
    uh.y = (uint32_t)__bfloat16_as_ushort(h2) | ((uint32_t)__bfloat16_as_ushort(h3) << 16);
    ul.x = (uint32_t)__bfloat16_as_ushort(l0) | ((uint32_t)__bfloat16_as_ushort(l1) << 16);
    ul.y = (uint32_t)__bfloat16_as_ushort(l2) | ((uint32_t)__bfloat16_as_ushort(l3) << 16);
    ((uint2*)hi)[i] = uh;
    ((uint2*)lo)[i] = ul;
}

// ---------------------------------------------------------------------------
// HMMA helpers (base PTX, legal at compute_103)
// ---------------------------------------------------------------------------
__device__ __forceinline__ uint32_t smem_u32(const void* p) {
    uint32_t a;
    asm("{ .reg .u64 t; cvta.to.shared.u64 t, %1; cvt.u32.u64 %0, t; }"
        : "=r"(a) : "l"(p));
    return a;
}
__device__ __forceinline__ void cp16(uint32_t dst, const void* src) {
    asm volatile("cp.async.cg.shared.global [%0], [%1], 16;"
                 :: "r"(dst), "l"(src));
}
__device__ __forceinline__ void ldm4(uint32_t* r, uint32_t a) {
    asm volatile("ldmatrix.sync.aligned.m8n8.x4.shared.b16 {%0,%1,%2,%3}, [%4];"
                 : "=r"(r[0]), "=r"(r[1]), "=r"(r[2]), "=r"(r[3]) : "r"(a));
}
__device__ __forceinline__ void ldm4t(uint32_t* r, uint32_t a) {
    asm volatile("ldmatrix.sync.aligned.m8n8.x4.trans.shared.b16 {%0,%1,%2,%3}, [%4];"
                 : "=r"(r[0]), "=r"(r[1]), "=r"(r[2]), "=r"(r[3]) : "r"(a));
}
__device__ __forceinline__ void mma16816(float* c, const uint32_t* a,
                                         uint32_t b0, uint32_t b1) {
    asm volatile(
        "mma.sync.aligned.m16n8k16.row.col.f32.bf16.bf16.f32 "
        "{%0,%1,%2,%3}, {%4,%5,%6,%7}, {%8,%9}, {%0,%1,%2,%3};"
        : "+f"(c[0]), "+f"(c[1]), "+f"(c[2]), "+f"(c[3])
        : "r"(a[0]), "r"(a[1]), "r"(a[2]), "r"(a[3]), "r"(b0), "r"(b1));
}
__device__ __forceinline__ uint32_t packbf(float lo, float hi) {
    uint32_t r;
    asm("cvt.rn.bf16x2.f32 %0, %1, %2;" : "=r"(r) : "f"(hi), "f"(lo));
    return r;
}

// ---------------------------------------------------------------------------
// bf16-split GEMM via mma.sync: C[M,N] = A[M,K] @ B[N,K]^T (+R)
// ---------------------------------------------------------------------------
#define LDSP    80
#define ARRSZ   10240
#define STAGE   40960
#define MG_SMEM (2 * STAGE)

__global__ __launch_bounds__(256, 2) void mma_gemm_kernel(
    const __nv_bfloat16* __restrict__ Ah, const __nv_bfloat16* __restrict__ Al,
    const __nv_bfloat16* __restrict__ Bh, const __nv_bfloat16* __restrict__ Bl,
    const float* __restrict__ R, float* __restrict__ C,
    int M, int N, int K) {
    extern __shared__ char smx[];
    uint32_t sb = smem_u32(smx);
    int tid = threadIdx.x, wid = tid >> 5, lane = tid & 31;
    int bm = blockIdx.y * 128, bn = blockIdx.x * 128;
    int wm = (wid & 3) * 32, wn = (wid >> 2) * 64;

    const __nv_bfloat16* pAh = Ah + (size_t)bm * K;
    const __nv_bfloat16* pAl = Al + (size_t)bm * K;
    const __nv_bfloat16* pBh = Bh + (size_t)bn * K;
    const __nv_bfloat16* pBl = Bl + (size_t)bn * K;

    float acc[2][8][4];
#pragma unroll
    for (int i = 0; i < 2; i++)
#pragma unroll
        for (int j = 0; j < 8; j++)
#pragma unroll
            for (int t = 0; t < 4; t++) acc[i][j][t] = 0.f;

    int nch = K >> 5;
    int jrow0 = tid >> 2;
    int jrow1 = 64 + (tid >> 2);
    int kb = (tid & 3);

#define LOADCHUNK(c, s)                                                        \
    {                                                                          \
        int k0 = (c) << 5;                                                     \
        uint32_t stg = sb + (s) * STAGE;                                       \
        {                                                                      \
            uint32_t db = stg + jrow0 * LDSP + kb * 16;                        \
            size_t go = (size_t)jrow0 * K + k0 + kb * 8;                       \
            cp16(db, pAh + go);                                                \
            cp16(db + ARRSZ, pAl + go);                                        \
            cp16(db + 2 * ARRSZ, pBh + go);                                    \
            cp16(db + 3 * ARRSZ, pBl + go);                                    \
        }                                                                      \
        {                                                                      \
            uint32_t db = stg + jrow1 * LDSP + kb * 16;                        \
            size_t go = (size_t)jrow1 * K + k0 + kb * 8;                       \
            cp16(db, pAh + go);                                                \
            cp16(db + ARRSZ, pAl + go);                                        \
            cp16(db + 2 * ARRSZ, pBh + go);                                    \
            cp16(db + 3 * ARRSZ, pBl + go);                                    \
        }                                                                      \
        asm volatile("cp.async.commit_group;");                                \
    }

    LOADCHUNK(0, 0)

    for (int c = 0; c < nch; c++) {
        int s = c & 1;
        if (c + 1 < nch) {
            LOADCHUNK(c + 1, s ^ 1)
            asm volatile("cp.async.wait_group 1;");
        } else {
            asm volatile("cp.async.wait_group 0;");
        }
        __syncthreads();

        uint32_t stg = sb + s * STAGE;
#pragma unroll
        for (int ks = 0; ks < 2; ks++) {
            uint32_t ar = stg + (wm + (lane & 15)) * LDSP
                        + (ks * 16 + (lane >> 4) * 8) * 2;
            uint32_t ahf[2][4], alf[2][4];
            ldm4(ahf[0], ar);
            ldm4(ahf[1], ar + 16 * LDSP);
            ldm4(alf[0], ar + ARRSZ);
            ldm4(alf[1], ar + ARRSZ + 16 * LDSP);
            uint32_t br = stg + 2 * ARRSZ
                        + (wn + (lane & 7) + ((lane >> 4) & 1) * 8) * LDSP
                        + (ks * 16 + ((lane >> 3) & 1) * 8) * 2;
#pragma unroll
            for (int pass = 0; pass < 3; pass++) {
                uint32_t boff = (pass == 1) ? ARRSZ : 0u;
#pragma unroll
                for (int g = 0; g < 4; g++) {
                    uint32_t b[4];
                    ldm4(b, br + boff + g * 16 * LDSP);
                    if (pass == 2) {
                        mma16816(acc[0][2 * g],     alf[0], b[0], b[1]);
                        mma16816(acc[0][2 * g + 1], alf[0], b[2], b[3]);
                        mma16816(acc[1][2 * g],     alf[1], b[0], b[1]);
                        mma16816(acc[1][2 * g + 1], alf[1], b[2], b[3]);
                    } else {
                        mma16816(acc[0][2 * g],     ahf[0], b[0], b[1]);
                        mma16816(acc[0][2 * g + 1], ahf[0], b[2], b[3]);
                        mma16816(acc[1][2 * g],     ahf[1], b[0], b[1]);
                        mma16816(acc[1][2 * g + 1], ahf[1], b[2], b[3]);
                    }
                }
            }
        }
        __syncthreads();
    }

#pragma unroll
    for (int mt = 0; mt < 2; mt++) {
        int m0 = bm + wm + mt * 16 + (lane >> 2);
#pragma unroll
        for (int nt = 0; nt < 8; nt++) {
            int n0 = bn + wn + nt * 8 + (lane & 3) * 2;
            float2 v0 = make_float2(acc[mt][nt][0], acc[mt][nt][1]);
            float2 v1 = make_float2(acc[mt][nt][2], acc[mt][nt][3]);
            if (R) {
                float2 r0 = *(const float2*)(R + (size_t)m0 * N + n0);
                float2 r1 = *(const float2*)(R + (size_t)(m0 + 8) * N + n0);
                v0.x += r0.x; v0.y += r0.y;
                v1.x += r1.x; v1.y += r1.y;
            }
            *(float2*)(C + (size_t)m0 * N + n0) = v0;
            *(float2*)(C + (size_t)(m0 + 8) * N + n0) = v1;
        }
    }
}

// ---------------------------------------------------------------------------
// RoPE table (double-precision sincos; fast-math-proof)
// ---------------------------------------------------------------------------
__global__ void rope_table_kernel(float2* __restrict__ tab) {
    int idx = blockIdx.x * blockDim.x + threadIdx.x;
    if (idx >= S_ * 32) return;
    int s = idx >> 5;
    int i = idx & 31;
    double invf = exp2(-(double)(2 * i) * (13.287712379549449 / 64.0));
    double ang = (double)s * invf;
    double sd, cd;
    sincos(ang, &sd, &cd);
    tab[idx] = make_float2((float)cd, (float)sd);
}

// ---------------------------------------------------------------------------
// RMSNorm
// ---------------------------------------------------------------------------
__global__ __launch_bounds__(256) void rmsnorm_kernel(
    const float* __restrict__ x, const float* __restrict__ w,
    float* __restrict__ out) {
    int row = blockIdx.x;
    const float4* xr = (const float4*)(x + (size_t)row * D_);
    int i = threadIdx.x;
    float4 xv = xr[i];
    float ss = xv.x * xv.x + xv.y * xv.y + xv.z * xv.z + xv.w * xv.w;
#pragma unroll
    for (int off = 16; off > 0; off >>= 1)
        ss += __shfl_xor_sync(0xffffffffu, ss, off);
    __shared__ float red[8];
    __shared__ float s_inv;
    if ((threadIdx.x & 31) == 0) red[threadIdx.x >> 5] = ss;
    __syncthreads();
    if (threadIdx.x == 0) {
        float t = 0.f;
#pragma unroll
        for (int j = 0; j < 8; j++) t += red[j];
        s_inv = rsqrtf(t * (1.0f / D_) + 1e-5f);
    }
    __syncthreads();
    float inv = s_inv;
    float4 wv = ((const float4*)w)[i];
    float4 r;
    r.x = inv * xv.x * wv.x;
    r.y = inv * xv.y * wv.y;
    r.z = inv * xv.z * wv.z;
    r.w = inv * xv.w * wv.w;
    ((float4*)(out + (size_t)row * D_))[i] = r;
}

// ---------------------------------------------------------------------------
// Fused: RoPE(q,k) + hi/lo split of q,k,v + [b,s,h,dk] -> [b,h,s,dk] repack
// ---------------------------------------------------------------------------
__global__ void qkv_prep_kernel(
    const float* __restrict__ q, const float* __restrict__ k,
    const float* __restrict__ v, const float2* __restrict__ tab,
    __nv_bfloat16* __restrict__ sh, __nv_bfloat16* __restrict__ sl) {
    int idx = blockIdx.x * blockDim.x + threadIdx.x;
    if (idx >= M_ * D_ / 2) return;
    int e = idx * 2;
    int m = e >> 10;
    int d = e & (D_ - 1);
    int s = m & (S_ - 1);
    int b = m >> 11;
    int hh = d >> 6;
    int dk = d & (DK_ - 1);           // even
    float2 cs = tab[(s << 5) + (dk >> 1)];
    size_t p = (size_t)m * D_ + d;
    size_t o = ((size_t)(b * H_ + hh) * S_ + s) * DK_ + dk;  // even -> 4B aligned

    float2 qv = *(const float2*)(q + p);
    float2 kv = *(const float2*)(k + p);
    float2 vv = *(const float2*)(v + p);
    float qe = cs.x * qv.x - cs.y * qv.y;
    float qo = cs.y * qv.x + cs.x * qv.y;
    float ke = cs.x * kv.x - cs.y * kv.y;
    float ko = cs.y * kv.x + cs.x * kv.y;

    __nv_bfloat16 qeh = __float2bfloat16(qe), qoh = __float2bfloat16(qo);
    __nv_bfloat16 keh = __float2bfloat16(ke), koh = __float2bfloat16(ko);
    __nv_bfloat16 veh = __float2bfloat16(vv.x), voh = __float2bfloat16(vv.y);
    uint32_t qhp = (uint32_t)__bfloat16_as_ushort(qeh) | ((uint32_t)__bfloat16_as_ushort(qoh) << 16);
    uint32_t khp = (uint32_t)__bfloat16_as_ushort(keh) | ((uint32_t)__bfloat16_as_ushort(koh) << 16);
    uint32_t vhp = (uint32_t)__bfloat16_as_ushort(veh) | ((uint32_t)__bfloat16_as_ushort(voh) << 16);
    uint32_t qlp = packbf(qe - __bfloat162float(qeh), qo - __bfloat162float(qoh));
    uint32_t klp = packbf(ke - __bfloat162float(keh), ko - __bfloat162float(koh));
    uint32_t vlp = packbf(vv.x - __bfloat162float(veh), vv.y - __bfloat162float(voh));

    *(uint32_t*)(sh + OQ_ + o) = qhp;
    *(uint32_t*)(sl + OQ_ + o) = qlp;
    *(uint32_t*)(sh + OK_ + o) = khp;
    *(uint32_t*)(sl + OK_ + o) = klp;
    *(uint32_t*)(sh + OV_ + o) = vhp;
    *(uint32_t*)(sl + OV_ + o) = vlp;
}

// ---------------------------------------------------------------------------
// HMMA causal flash attention.
// Grid (S/64, H, B), 128 threads (4 warps x 16 q rows).
// Scores: 3-pass bf16 split (qh*kh + qh*kl + ql*kh); PV: P*(vh+vl).
// ---------------------------------------------------------------------------
#define AP    144            // smem pitch bytes (64 bf16 row + 16B pad)
#define AARR  9216           // 64 * 144
#define SQH   0
#define SQL   9216
#define SKH   18432
#define SKL   27648
#define SVH   36864
#define SVL   46080
#define AT_SMEM 55296

__global__ __launch_bounds__(128, 2) void attn_mma_kernel(
    const __nv_bfloat16* __restrict__ sh, const __nv_bfloat16* __restrict__ sl,
    float* __restrict__ O) {
    extern __shared__ char smx[];
    uint32_t sb = smem_u32(smx);
    int tid = threadIdx.x, w = tid >> 5, lane = tid & 31;
    int qt = gridDim.x - 1 - blockIdx.x;   // long CTAs first
    int h = blockIdx.y, b = blockIdx.z;
    size_t base = (size_t)(b * H_ + h) * S_;   // row offset in [b,h,s,dk]
    int s0 = qt * 64;

    const __nv_bfloat16* qh = sh + OQ_;
    const __nv_bfloat16* ql = sl + OQ_;
    const __nv_bfloat16* kh = sh + OK_;
    const __nv_bfloat16* kl = sl + OK_;
    const __nv_bfloat16* vh = sh + OV_;
    const __nv_bfloat16* vl = sl + OV_;

    // stage Q tile (64 x 64)
#pragma unroll
    for (int i = 0; i < 4; i++) {
        int idx = i * 128 + tid;
        int row = idx >> 3, c = idx & 7;
        size_t go = (base + s0 + row) * DK_ + c * 8;
        cp16(sb + SQH + row * AP + c * 16, qh + go);
        cp16(sb + SQL + row * AP + c * 16, ql + go);
    }
    asm volatile("cp.async.commit_group;");
    asm volatile("cp.async.wait_group 0;");
    __syncthreads();

    // Q fragments (4 k16 steps x 4 regs, hi and lo)
    uint32_t qfh[4][4], qfl[4][4];
#pragma unroll
    for (int ks = 0; ks < 4; ks++) {
        uint32_t ar = sb + SQH + (16 * w + (lane & 15)) * AP
                    + (ks * 16 + (lane >> 4) * 8) * 2;
        ldm4(qfh[ks], ar);
        ldm4(qfl[ks], ar + (SQL - SQH));
    }

    float oacc[8][4];
#pragma unroll
    for (int j = 0; j < 8; j++)
#pragma unroll
        for (int t = 0; t < 4; t++) oacc[j][t] = 0.f;
    float m0 = -INFINITY, m1 = -INFINITY, l0 = 0.f, l1 = 0.f;
    int q0 = s0 + 16 * w + (lane >> 2);    // global q row (low half)

    for (int kvt = 0; kvt <= qt; kvt++) {
        int kv0 = kvt * 64;
        __syncthreads();   // prior iter's ldmatrix reads done before overwrite
#pragma unroll
        for (int i = 0; i < 4; i++) {
            int idx = i * 128 + tid;
            int row = idx >> 3, c = idx & 7;
            size_t go = (base + kv0 + row) * DK_ + c * 8;
            uint32_t db = sb + row * AP + c * 16;
            cp16(db + SKH, kh + go);
            cp16(db + SKL, kl + go);
            cp16(db + SVH, vh + go);
            cp16(db + SVL, vl + go);
        }
        asm volatile("cp.async.commit_group;");
        asm volatile("cp.async.wait_group 0;");
        __syncthreads();

        // scores: 64q x 64k
        float sacc[8][4];
#pragma unroll
        for (int j = 0; j < 8; j++)
#pragma unroll
            for (int t = 0; t < 4; t++) sacc[j][t] = 0.f;
#pragma unroll
        for (int ks = 0; ks < 4; ks++) {
            uint32_t br = sb + SKH + ((lane & 7) + ((lane >> 4) & 1) * 8) * AP
                        + (ks * 16 + ((lane >> 3) & 1) * 8) * 2;
#pragma unroll
            for (int g = 0; g < 4; g++) {
                uint32_t bh4[4], bl4[4];
                ldm4(bh4, br + g * 16 * AP);
                ldm4(bl4, br + g * 16 * AP + (SKL - SKH));
                mma16816(sacc[2 * g],     qfh[ks], bh4[0], bh4[1]);
                mma16816(sacc[2 * g + 1], qfh[ks], bh4[2], bh4[3]);
                mma16816(sacc[2 * g],     qfh[ks], bl4[0], bl4[1]);
                mma16816(sacc[2 * g + 1], qfh[ks], bl4[2], bl4[3]);
                mma16816(sacc[2 * g],     qfl[ks], bh4[0], bh4[1]);
                mma16816(sacc[2 * g + 1], qfl[ks], bh4[2], bh4[3]);
            }
        }
        // scale + causal mask (diagonal tile only)
#pragma unroll
        for (int j = 0; j < 8; j++)
#pragma unroll
            for (int t = 0; t < 4; t++) sacc[j][t] *= 0.125f;
        if (kvt == qt) {
            int cb = kv0 + 2 * (lane & 3);
#pragma unroll
            for (int j = 0; j < 8; j++) {
                int kc = cb + 8 * j;
                if (kc     > q0)     sacc[j][0] = -INFINITY;
                if (kc + 1 > q0)     sacc[j][1] = -INFINITY;
                if (kc     > q0 + 8) sacc[j][2] = -INFINITY;
                if (kc + 1 > q0 + 8) sacc[j][3] = -INFINITY;
            }
        }
        // online softmax
        float mx0 = -INFINITY, mx1 = -INFINITY;
#pragma unroll
        for (int j = 0; j < 8; j++) {
            mx0 = fmaxf(mx0, fmaxf(sacc[j][0], sacc[j][1]));
            mx1 = fmaxf(mx1, fmaxf(sacc[j][2], sacc[j][3]));
        }
        mx0 = fmaxf(mx0, __shfl_xor_sync(0xffffffffu, mx0, 1));
        mx0 = fmaxf(mx0, __shfl_xor_sync(0xffffffffu, mx0, 2));
        mx1 = fmaxf(mx1, __shfl_xor_sync(0xffffffffu, mx1, 1));
        mx1 = fmaxf(mx1, __shfl_xor_sync(0xffffffffu, mx1, 2));
        float mn0 = fmaxf(m0, mx0), mn1 = fmaxf(m1, mx1);
        float cr0 = __expf(m0 - mn0), cr1 = __expf(m1 - mn1);
        l0 *= cr0; l1 *= cr1;
#pragma unroll
        for (int j = 0; j < 8; j++) {
            oacc[j][0] *= cr0; oacc[j][1] *= cr0;
            oacc[j][2] *= cr1; oacc[j][3] *= cr1;
        }
        uint32_t pf[4][4];
#pragma unroll
        for (int j = 0; j < 8; j++) {
            float p0 = __expf(sacc[j][0] - mn0);
            float p1 = __expf(sacc[j][1] - mn0);
            float p2 = __expf(sacc[j][2] - mn1);
            float p3 = __expf(sacc[j][3] - mn1);
            l0 += p0 + p1; l1 += p2 + p3;
            pf[j >> 1][(j & 1) * 2]     = packbf(p0, p1);
            pf[j >> 1][(j & 1) * 2 + 1] = packbf(p2, p3);
        }
        m0 = mn0; m1 = mn1;
        // PV: o += P * (Vh + Vl)
#pragma unroll
        for (int kt = 0; kt < 4; kt++) {
            uint32_t va = sb + SVH + (kt * 16 + (lane & 15)) * AP
                        + ((lane >> 4) * 8) * 2;
#pragma unroll
            for (int gn = 0; gn < 4; gn++) {
                uint32_t vb[4];
                ldm4t(vb, va + gn * 32);
                mma16816(oacc[2 * gn],     pf[kt], vb[0], vb[1]);
                mma16816(oacc[2 * gn + 1], pf[kt], vb[2], vb[3]);
                ldm4t(vb, va + gn * 32 + (SVL - SVH));
                mma16816(oacc[2 * gn],     pf[kt], vb[0], vb[1]);
                mma16816(oacc[2 * gn + 1], pf[kt], vb[2], vb[3]);
            }
        }
    }

    l0 += __shfl_xor_sync(0xffffffffu, l0, 1);
    l0 += __shfl_xor_sync(0xffffffffu, l0, 2);
    l1 += __shfl_xor_sync(0xffffffffu, l1, 1);
    l1 += __shfl_xor_sync(0xffffffffu, l1, 2);
    float i0 = 1.f / l0, i1 = 1.f / l1;

    float* o0 = O + (size_t)(b * S_ + q0) * D_ + h * DK_;
    float* o1 = O + (size_t)(b * S_ + q0 + 8) * D_ + h * DK_;
#pragma unroll
    for (int j = 0; j < 8; j++) {
        int dk0 = 8 * j + 2 * (lane & 3);
        *(float2*)(o0 + dk0) = make_float2(oacc[j][0] * i0, oacc[j][1] * i0);
        *(float2*)(o1 + dk0) = make_float2(oacc[j][2] * i1, oacc[j][3] * i1);
    }
}

// ---------------------------------------------------------------------------
// SwiGLU
// ---------------------------------------------------------------------------
__global__ void swiglu_kernel(float* __restrict__ u, const float* __restrict__ g, int n4) {
    int i = blockIdx.x * blockDim.x + threadIdx.x;
    if (i >= n4) return;
    float4 uv = ((const float4*)u)[i];
    float4 gv = ((const float4*)g)[i];
    float4 r;
    r.x = uv.x * (1.0f / (1.0f + expf(-uv.x))) * gv.x;
    r.y = uv.y * (1.0f / (1.0f + expf(-uv.y))) * gv.y;
    r.z = uv.z * (1.0f / (1.0f + expf(-uv.z))) * gv.z;
    r.w = uv.w * (1.0f / (1.0f + expf(-uv.w))) * gv.w;
    ((float4*)u)[i] = r;
}

// ---------------------------------------------------------------------------
// Launch
// ---------------------------------------------------------------------------
extern "C" void kernel_launch(void* const* d_in, const int* in_sizes, int n_in,
                              void* d_out, int out_size) {
    const float* x   = (const float*)d_in[0];
    const float* w_q = (const float*)d_in[1];
    const float* w_k = (const float*)d_in[2];
    const float* w_v = (const float*)d_in[3];
    const float* w_o = (const float*)d_in[4];
    const float* ln1 = (const float*)d_in[5];
    const float* ln2 = (const float*)d_in[6];
    const float* w1  = (const float*)d_in[7];
    const float* w2  = (const float*)d_in[8];
    const float* w3  = (const float*)d_in[9];
    float* out = (float*)d_out;

    float *h, *q, *k, *v, *attn, *x2, *u, *gp;
    float2* rope;
    __nv_bfloat16 *sh, *sl, *wh, *wl;
    cudaGetSymbolAddress((void**)&h,    g_h);
    cudaGetSymbolAddress((void**)&q,    g_q);
    cudaGetSymbolAddress((void**)&k,    g_k);
    cudaGetSymbolAddress((void**)&v,    g_v);
    cudaGetSymbolAddress((void**)&attn, g_attn);
    cudaGetSymbolAddress((void**)&x2,   g_x2);
    cudaGetSymbolAddress((void**)&u,    g_u);
    cudaGetSymbolAddress((void**)&gp,   g_g);
    cudaGetSymbolAddress((void**)&rope, g_rope);
    cudaGetSymbolAddress((void**)&sh,   g_sh);
    cudaGetSymbolAddress((void**)&sl,   g_sl);
    cudaGetSymbolAddress((void**)&wh,   g_wh);
    cudaGetSymbolAddress((void**)&wl,   g_wl);

    cudaFuncSetAttribute(mma_gemm_kernel,
                         cudaFuncAttributeMaxDynamicSharedMemorySize, MG_SMEM);
    cudaFuncSetAttribute(attn_mma_kernel,
                         cudaFuncAttributeMaxDynamicSharedMemorySize, AT_SMEM);

    // 0) RoPE table + weight splits
    rope_table_kernel<<<(S_ * 32 + 255) / 256, 256>>>(rope);
    split_kernel<<<1024, 256>>>(w_q, wh + OW_Q, wl + OW_Q, 262144);
    split_kernel<<<1024, 256>>>(w_k, wh + OW_K, wl + OW_K, 262144);
    split_kernel<<<1024, 256>>>(w_v, wh + OW_V, wl + OW_V, 262144);
    split_kernel<<<1024, 256>>>(w_o, wh + OW_O, wl + OW_O, 262144);
    split_kernel<<<4096, 256>>>(w1,  wh + OW_1, wl + OW_1, 1048576);
    split_kernel<<<4096, 256>>>(w3,  wh + OW_3, wl + OW_3, 1048576);
    split_kernel<<<4096, 256>>>(w2,  wh + OW_2, wl + OW_2, 1048576);

    // 1) h = rmsnorm(x, ln1); split
    rmsnorm_kernel<<<M_, 256>>>(x, ln1, h);
    split_kernel<<<4096, 256>>>(h, sh, sl, 1048576);

    // 2) q/k/v = h @ w^T
    dim3 gProj(D_ / 128, M_ / 128);
    mma_gemm_kernel<<<gProj, 256, MG_SMEM>>>(sh, sl, wh + OW_Q, wl + OW_Q, nullptr, q, M_, D_, D_);
    mma_gemm_kernel<<<gProj, 256, MG_SMEM>>>(sh, sl, wh + OW_K, wl + OW_K, nullptr, k, M_, D_, D_);
    mma_gemm_kernel<<<gProj, 256, MG_SMEM>>>(sh, sl, wh + OW_V, wl + OW_V, nullptr, v, M_, D_, D_);

    // 3) RoPE + split + repack q/k/v  (overwrites h-split; GEMMs above are done)
    qkv_prep_kernel<<<(M_ * D_ / 2 + 255) / 256, 256>>>(q, k, v, rope, sh, sl);

    // 4) HMMA causal flash attention
    attn_mma_kernel<<<dim3(S_ / 64, H_, B_), 128, AT_SMEM>>>(sh, sl, attn);

    // 5) x2 = x + attn @ w_o^T
    split_kernel<<<4096, 256>>>(attn, sh, sl, 1048576);
    mma_gemm_kernel<<<gProj, 256, MG_SMEM>>>(sh, sl, wh + OW_O, wl + OW_O, x, x2, M_, D_, D_);

    // 6) h = rmsnorm(x2, ln2); split
    rmsnorm_kernel<<<M_, 256>>>(x2, ln2, h);
    split_kernel<<<4096, 256>>>(h, sh, sl, 1048576);

    // 7) u = h @ w1^T ; g = h @ w3^T
    dim3 gFF(DFF_ / 128, M_ / 128);
    mma_gemm_kernel<<<gFF, 256, MG_SMEM>>>(sh, sl, wh + OW_1, wl + OW_1, nullptr, u,  M_, DFF_, D_);
    mma_gemm_kernel<<<gFF, 256, MG_SMEM>>>(sh, sl, wh + OW_3, wl + OW_3, nullptr, gp, M_, DFF_, D_);

    // 8) u = u * sigmoid(u) * g ; split
    swiglu_kernel<<<(M_ * DFF_ / 4 + 255) / 256, 256>>>(u, gp, M_ * DFF_ / 4);
    split_kernel<<<16384, 256>>>(u, sh, sl, 4194304);

    // 9) out = x2 + u @ w2^T
    mma_gemm_kernel<<<gProj, 256, MG_SMEM>>>(sh, sl, wh + OW_2, wl + OW_2, x2, out, M_, D_, DFF_);
}

// round 7
// speedup vs baseline: 3.3831x; 1.0051x over previous
#include <cuda_runtime.h>
#include <cuda_bf16.h>
#include <math.h>
#include <stdint.h>

// Problem dims (fixed by the reference)
#define B_   2
#define S_   2048
#define D_   1024
#define H_   16
#define DK_  64
#define DFF_ 4096
#define M_   (B_ * S_)   // 4096 tokens

// ---------------------------------------------------------------------------
// Scratch (device globals)
// ---------------------------------------------------------------------------
__device__ float g_ffn[M_ * 2 * DFF_];   // FFN u|g combined; also qkv fp32 [M,3072]
__device__ float g_x2 [M_ * D_];
__device__ float2 g_rope[S_ * 32];

#define ASZ (16u * 1048576u)
#define WSZ (16u * 1048576u)
__device__ __nv_bfloat16 g_sh[ASZ];
__device__ __nv_bfloat16 g_sl[ASZ];
__device__ __nv_bfloat16 g_wh[WSZ];
__device__ __nv_bfloat16 g_wl[WSZ];

// weight offsets (elements); Q,K,V contiguous; W1,W3 contiguous
#define OW_Q  0u
#define OW_K  1048576u
#define OW_V  2097152u
#define OW_O  3145728u
#define OW_1  4194304u
#define OW_3  8388608u
#define OW_2  12582912u
// activation-split regions in g_sh/g_sl during attention
#define OQ_   0u
#define OK_   4194304u
#define OV_   8388608u
#define OA_   12582912u

// ---------------------------------------------------------------------------
// helpers
// ---------------------------------------------------------------------------
__device__ __forceinline__ uint32_t smem_u32(const void* p) {
    uint32_t a;
    asm("{ .reg .u64 t; cvta.to.shared.u64 t, %1; cvt.u32.u64 %0, t; }"
        : "=r"(a) : "l"(p));
    return a;
}
__device__ __forceinline__ void cp16(uint32_t dst, const void* src) {
    asm volatile("cp.async.cg.shared.global [%0], [%1], 16;"
                 :: "r"(dst), "l"(src));
}
__device__ __forceinline__ void ldm4(uint32_t* r, uint32_t a) {
    asm volatile("ldmatrix.sync.aligned.m8n8.x4.shared.b16 {%0,%1,%2,%3}, [%4];"
                 : "=r"(r[0]), "=r"(r[1]), "=r"(r[2]), "=r"(r[3]) : "r"(a));
}
__device__ __forceinline__ void ldm4t(uint32_t* r, uint32_t a) {
    asm volatile("ldmatrix.sync.aligned.m8n8.x4.trans.shared.b16 {%0,%1,%2,%3}, [%4];"
                 : "=r"(r[0]), "=r"(r[1]), "=r"(r[2]), "=r"(r[3]) : "r"(a));
}
__device__ __forceinline__ void mma16816(float* c, const uint32_t* a,
                                         uint32_t b0, uint32_t b1) {
    asm volatile(
        "mma.sync.aligned.m16n8k16.row.col.f32.bf16.bf16.f32 "
        "{%0,%1,%2,%3}, {%4,%5,%6,%7}, {%8,%9}, {%0,%1,%2,%3};"
        : "+f"(c[0]), "+f"(c[1]), "+f"(c[2]), "+f"(c[3])
        : "r"(a[0]), "r"(a[1]), "r"(a[2]), "r"(a[3]), "r"(b0), "r"(b1));
}
__device__ __forceinline__ uint32_t packbf(float lo, float hi) {
    uint32_t r;
    asm("cvt.rn.bf16x2.f32 %0, %1, %2;" : "=r"(r) : "f"(hi), "f"(lo));
    return r;
}
// split one float into bf16 hi/lo
__device__ __forceinline__ void split1(float v, float& rh, float& rl) {
    __nv_bfloat16 hb = __float2bfloat16(v);
    rh = __bfloat162float(hb);
    rl = v - rh;
}
__device__ __forceinline__ void split4_pack(const float4 v, uint2& uh, uint2& ul) {
    float h0, l0, h1, l1, h2, l2, h3, l3;
    split1(v.x, h0, l0); split1(v.y, h1, l1);
    split1(v.z, h2, l2); split1(v.w, h3, l3);
    uh.x = packbf(h0, h1); uh.y = packbf(h2, h3);
    ul.x = packbf(l0, l1); ul.y = packbf(l2, l3);
}

// ---------------------------------------------------------------------------
// weight split, MLP=4 (thread t handles units t, t+q, t+2q, t+3q)
// ---------------------------------------------------------------------------
__global__ void wsplit_kernel(const float* __restrict__ s,
                              __nv_bfloat16* __restrict__ hi,
                              __nv_bfloat16* __restrict__ lo, int n4) {
    int q = n4 >> 2;
    int t = blockIdx.x * blockDim.x + threadIdx.x;
    if (t >= q) return;
    float4 v0 = ((const float4*)s)[t];
    float4 v1 = ((const float4*)s)[t + q];
    float4 v2 = ((const float4*)s)[t + 2 * q];
    float4 v3 = ((const float4*)s)[t + 3 * q];
    uint2 h0, l0, h1, l1, h2, l2, h3, l3;
    split4_pack(v0, h0, l0); split4_pack(v1, h1, l1);
    split4_pack(v2, h2, l2); split4_pack(v3, h3, l3);
    ((uint2*)hi)[t]         = h0; ((uint2*)lo)[t]         = l0;
    ((uint2*)hi)[t + q]     = h1; ((uint2*)lo)[t + q]     = l1;
    ((uint2*)hi)[t + 2 * q] = h2; ((uint2*)lo)[t + 2 * q] = l2;
    ((uint2*)hi)[t + 3 * q] = h3; ((uint2*)lo)[t + 3 * q] = l3;
}

// ---------------------------------------------------------------------------
// bf16-split GEMM via mma.sync: C[M,N] = A[M,K] @ B[N,K]^T (+R)
// ---------------------------------------------------------------------------
#define LDSP    80
#define ARRSZ   10240
#define STAGE   40960
#define MG_SMEM (2 * STAGE)

__global__ __launch_bounds__(256, 2) void mma_gemm_kernel(
    const __nv_bfloat16* __restrict__ Ah, const __nv_bfloat16* __restrict__ Al,
    const __nv_bfloat16* __restrict__ Bh, const __nv_bfloat16* __restrict__ Bl,
    const float* __restrict__ R, float* __restrict__ C,
    int M, int N, int K) {
    extern __shared__ char smx[];
    uint32_t sb = smem_u32(smx);
    int tid = threadIdx.x, wid = tid >> 5, lane = tid & 31;
    int bm = blockIdx.y * 128, bn = blockIdx.x * 128;
    int wm = (wid & 3) * 32, wn = (wid >> 2) * 64;

    const __nv_bfloat16* pAh = Ah + (size_t)bm * K;
    const __nv_bfloat16* pAl = Al + (size_t)bm * K;
    const __nv_bfloat16* pBh = Bh + (size_t)bn * K;
    const __nv_bfloat16* pBl = Bl + (size_t)bn * K;

    float acc[2][8][4];
#pragma unroll
    for (int i = 0; i < 2; i++)
#pragma unroll
        for (int j = 0; j < 8; j++)
#pragma unroll
            for (int t = 0; t < 4; t++) acc[i][j][t] = 0.f;

    int nch = K >> 5;
    int jrow0 = tid >> 2;
    int jrow1 = 64 + (tid >> 2);
    int kb = (tid & 3);

#define LOADCHUNK(c, s)                                                        \
    {                                                                          \
        int k0 = (c) << 5;                                                     \
        uint32_t stg = sb + (s) * STAGE;                                       \
        {                                                                      \
            uint32_t db = stg + jrow0 * LDSP + kb * 16;                        \
            size_t go = (size_t)jrow0 * K + k0 + kb * 8;                       \
            cp16(db, pAh + go);                                                \
            cp16(db + ARRSZ, pAl + go);                                        \
            cp16(db + 2 * ARRSZ, pBh + go);                                    \
            cp16(db + 3 * ARRSZ, pBl + go);                                    \
        }                                                                      \
        {                                                                      \
            uint32_t db = stg + jrow1 * LDSP + kb * 16;                        \
            size_t go = (size_t)jrow1 * K + k0 + kb * 8;                       \
            cp16(db, pAh + go);                                                \
            cp16(db + ARRSZ, pAl + go);                                        \
            cp16(db + 2 * ARRSZ, pBh + go);                                    \
            cp16(db + 3 * ARRSZ, pBl + go);                                    \
        }                                                                      \
        asm volatile("cp.async.commit_group;");                                \
    }

    LOADCHUNK(0, 0)

    for (int c = 0; c < nch; c++) {
        int s = c & 1;
        if (c + 1 < nch) {
            LOADCHUNK(c + 1, s ^ 1)
            asm volatile("cp.async.wait_group 1;");
        } else {
            asm volatile("cp.async.wait_group 0;");
        }
        __syncthreads();

        uint32_t stg = sb + s * STAGE;
#pragma unroll
        for (int ks = 0; ks < 2; ks++) {
            uint32_t ar = stg + (wm + (lane & 15)) * LDSP
                        + (ks * 16 + (lane >> 4) * 8) * 2;
            uint32_t ahf[2][4], alf[2][4];
            ldm4(ahf[0], ar);
            ldm4(ahf[1], ar + 16 * LDSP);
            ldm4(alf[0], ar + ARRSZ);
            ldm4(alf[1], ar + ARRSZ + 16 * LDSP);
            uint32_t br = stg + 2 * ARRSZ
                        + (wn + (lane & 7) + ((lane >> 4) & 1) * 8) * LDSP
                        + (ks * 16 + ((lane >> 3) & 1) * 8) * 2;
#pragma unroll
            for (int g = 0; g < 4; g++) {
                uint32_t bh4[4], bl4[4];
                ldm4(bh4, br + g * 16 * LDSP);
                ldm4(bl4, br + g * 16 * LDSP + ARRSZ);
                // hi*hi
                mma16816(acc[0][2 * g],     ahf[0], bh4[0], bh4[1]);
                mma16816(acc[0][2 * g + 1], ahf[0], bh4[2], bh4[3]);
                mma16816(acc[1][2 * g],     ahf[1], bh4[0], bh4[1]);
                mma16816(acc[1][2 * g + 1], ahf[1], bh4[2], bh4[3]);
                // hi*lo
                mma16816(acc[0][2 * g],     ahf[0], bl4[0], bl4[1]);
                mma16816(acc[0][2 * g + 1], ahf[0], bl4[2], bl4[3]);
                mma16816(acc[1][2 * g],     ahf[1], bl4[0], bl4[1]);
                mma16816(acc[1][2 * g + 1], ahf[1], bl4[2], bl4[3]);
                // lo*hi
                mma16816(acc[0][2 * g],     alf[0], bh4[0], bh4[1]);
                mma16816(acc[0][2 * g + 1], alf[0], bh4[2], bh4[3]);
                mma16816(acc[1][2 * g],     alf[1], bh4[0], bh4[1]);
                mma16816(acc[1][2 * g + 1], alf[1], bh4[2], bh4[3]);
            }
        }
        __syncthreads();
    }

#pragma unroll
    for (int mt = 0; mt < 2; mt++) {
        int m0 = bm + wm + mt * 16 + (lane >> 2);
#pragma unroll
        for (int nt = 0; nt < 8; nt++) {
            int n0 = bn + wn + nt * 8 + (lane & 3) * 2;
            float2 v0 = make_float2(acc[mt][nt][0], acc[mt][nt][1]);
            float2 v1 = make_float2(acc[mt][nt][2], acc[mt][nt][3]);
            if (R) {
                float2 r0 = *(const float2*)(R + (size_t)m0 * N + n0);
                float2 r1 = *(const float2*)(R + (size_t)(m0 + 8) * N + n0);
                v0.x += r0.x; v0.y += r0.y;
                v1.x += r1.x; v1.y += r1.y;
            }
            *(float2*)(C + (size_t)m0 * N + n0) = v0;
            *(float2*)(C + (size_t)(m0 + 8) * N + n0) = v1;
        }
    }
}

// ---------------------------------------------------------------------------
// RoPE table (double-precision sincos; fast-math-proof)
// ---------------------------------------------------------------------------
__global__ void rope_table_kernel(float2* __restrict__ tab) {
    int idx = blockIdx.x * blockDim.x + threadIdx.x;
    if (idx >= S_ * 32) return;
    int s = idx >> 5;
    int i = idx & 31;
    double invf = exp2(-(double)(2 * i) * (13.287712379549449 / 64.0));
    double ang = (double)s * invf;
    double sd, cd;
    sincos(ang, &sd, &cd);
    tab[idx] = make_float2((float)cd, (float)sd);
}

// ---------------------------------------------------------------------------
// RMSNorm fused with bf16 hi/lo split (writes split only)
// ---------------------------------------------------------------------------
__global__ __launch_bounds__(256) void rmsnorm_split_kernel(
    const float* __restrict__ x, const float* __restrict__ w,
    __nv_bfloat16* __restrict__ hi, __nv_bfloat16* __restrict__ lo) {
    int row = blockIdx.x;
    const float4* xr = (const float4*)(x + (size_t)row * D_);
    int i = threadIdx.x;
    float4 xv = xr[i];
    float ss = xv.x * xv.x + xv.y * xv.y + xv.z * xv.z + xv.w * xv.w;
#pragma unroll
    for (int off = 16; off > 0; off >>= 1)
        ss += __shfl_xor_sync(0xffffffffu, ss, off);
    __shared__ float red[8];
    __shared__ float s_inv;
    if ((threadIdx.x & 31) == 0) red[threadIdx.x >> 5] = ss;
    __syncthreads();
    if (threadIdx.x == 0) {
        float t = 0.f;
#pragma unroll
        for (int j = 0; j < 8; j++) t += red[j];
        s_inv = rsqrtf(t * (1.0f / D_) + 1e-5f);
    }
    __syncthreads();
    float inv = s_inv;
    float4 wv = ((const float4*)w)[i];
    float4 r;
    r.x = inv * xv.x * wv.x;
    r.y = inv * xv.y * wv.y;
    r.z = inv * xv.z * wv.z;
    r.w = inv * xv.w * wv.w;
    uint2 uh, ul;
    split4_pack(r, uh, ul);
    ((uint2*)(hi + (size_t)row * D_))[i] = uh;
    ((uint2*)(lo + (size_t)row * D_))[i] = ul;
}

// ---------------------------------------------------------------------------
// Fused: RoPE(q,k) + hi/lo split + [b,s,h,dk] -> [b,h,s,dk] repack.
// Reads combined qkv fp32 [m, 3072] (q|k|v).
// ---------------------------------------------------------------------------
__global__ void qkv_prep_kernel(
    const float* __restrict__ qkv, const float2* __restrict__ tab,
    __nv_bfloat16* __restrict__ sh, __nv_bfloat16* __restrict__ sl) {
    int idx = blockIdx.x * blockDim.x + threadIdx.x;
    if (idx >= M_ * D_ / 2) return;
    int e = idx * 2;
    int m = e >> 10;
    int d = e & (D_ - 1);
    int s = m & (S_ - 1);
    int b = m >> 11;
    int hh = d >> 6;
    int dk = d & (DK_ - 1);
    float2 cs = tab[(s << 5) + (dk >> 1)];
    size_t p = (size_t)m * 3072 + d;
    size_t o = ((size_t)(b * H_ + hh) * S_ + s) * DK_ + dk;

    float2 qv = *(const float2*)(qkv + p);
    float2 kv = *(const float2*)(qkv + p + 1024);
    float2 vv = *(const float2*)(qkv + p + 2048);
    float qe = cs.x * qv.x - cs.y * qv.y;
    float qo = cs.y * qv.x + cs.x * qv.y;
    float ke = cs.x * kv.x - cs.y * kv.y;
    float ko = cs.y * kv.x + cs.x * kv.y;

    float qeh, qel, qoh, qol, keh, kel, koh, kol, veh, vel, voh, vol;
    split1(qe, qeh, qel); split1(qo, qoh, qol);
    split1(ke, keh, kel); split1(ko, koh, kol);
    split1(vv.x, veh, vel); split1(vv.y, voh, vol);

    *(uint32_t*)(sh + OQ_ + o) = packbf(qeh, qoh);
    *(uint32_t*)(sl + OQ_ + o) = packbf(qel, qol);
    *(uint32_t*)(sh + OK_ + o) = packbf(keh, koh);
    *(uint32_t*)(sl + OK_ + o) = packbf(kel, kol);
    *(uint32_t*)(sh + OV_ + o) = packbf(veh, voh);
    *(uint32_t*)(sl + OV_ + o) = packbf(vel, vol);
}

// ---------------------------------------------------------------------------
// HMMA causal flash attention; epilogue writes bf16 hi/lo split directly.
// ---------------------------------------------------------------------------
#define AP    144
#define SQH   0
#define SQL   9216
#define SKH   18432
#define SKL   27648
#define SVH   36864
#define SVL   46080
#define AT_SMEM 55296

__global__ __launch_bounds__(128, 2) void attn_mma_kernel(
    const __nv_bfloat16* __restrict__ sh_in, const __nv_bfloat16* __restrict__ sl_in,
    __nv_bfloat16* __restrict__ oh, __nv_bfloat16* __restrict__ ol) {
    extern __shared__ char smx[];
    uint32_t sb = smem_u32(smx);
    int tid = threadIdx.x, w = tid >> 5, lane = tid & 31;
    int qt = gridDim.x - 1 - blockIdx.x;
    int h = blockIdx.y, b = blockIdx.z;
    size_t base = (size_t)(b * H_ + h) * S_;
    int s0 = qt * 64;

    const __nv_bfloat16* qh = sh_in + OQ_;
    const __nv_bfloat16* ql = sl_in + OQ_;
    const __nv_bfloat16* kh = sh_in + OK_;
    const __nv_bfloat16* kl = sl_in + OK_;
    const __nv_bfloat16* vh = sh_in + OV_;
    const __nv_bfloat16* vl = sl_in + OV_;

#pragma unroll
    for (int i = 0; i < 4; i++) {
        int idx = i * 128 + tid;
        int row = idx >> 3, c = idx & 7;
        size_t go = (base + s0 + row) * DK_ + c * 8;
        cp16(sb + SQH + row * AP + c * 16, qh + go);
        cp16(sb + SQL + row * AP + c * 16, ql + go);
    }
    asm volatile("cp.async.commit_group;");
    asm volatile("cp.async.wait_group 0;");
    __syncthreads();

    uint32_t qfh[4][4], qfl[4][4];
#pragma unroll
    for (int ks = 0; ks < 4; ks++) {
        uint32_t ar = sb + SQH + (16 * w + (lane & 15)) * AP
                    + (ks * 16 + (lane >> 4) * 8) * 2;
        ldm4(qfh[ks], ar);
        ldm4(qfl[ks], ar + (SQL - SQH));
    }

    float oacc[8][4];
#pragma unroll
    for (int j = 0; j < 8; j++)
#pragma unroll
        for (int t = 0; t < 4; t++) oacc[j][t] = 0.f;
    float m0 = -INFINITY, m1 = -INFINITY, l0 = 0.f, l1 = 0.f;
    int q0 = s0 + 16 * w + (lane >> 2);

    for (int kvt = 0; kvt <= qt; kvt++) {
        int kv0 = kvt * 64;
        __syncthreads();
#pragma unroll
        for (int i = 0; i < 4; i++) {
            int idx = i * 128 + tid;
            int row = idx >> 3, c = idx & 7;
            size_t go = (base + kv0 + row) * DK_ + c * 8;
            uint32_t db = sb + row * AP + c * 16;
            cp16(db + SKH, kh + go);
            cp16(db + SKL, kl + go);
            cp16(db + SVH, vh + go);
            cp16(db + SVL, vl + go);
        }
        asm volatile("cp.async.commit_group;");
        asm volatile("cp.async.wait_group 0;");
        __syncthreads();

        float sacc[8][4];
#pragma unroll
        for (int j = 0; j < 8; j++)
#pragma unroll
            for (int t = 0; t < 4; t++) sacc[j][t] = 0.f;
#pragma unroll
        for (int ks = 0; ks < 4; ks++) {
            uint32_t br = sb + SKH + ((lane & 7) + ((lane >> 4) & 1) * 8) * AP
                        + (ks * 16 + ((lane >> 3) & 1) * 8) * 2;
#pragma unroll
            for (int g = 0; g < 4; g++) {
                uint32_t bh4[4], bl4[4];
                ldm4(bh4, br + g * 16 * AP);
                ldm4(bl4, br + g * 16 * AP + (SKL - SKH));
                mma16816(sacc[2 * g],     qfh[ks], bh4[0], bh4[1]);
                mma16816(sacc[2 * g + 1], qfh[ks], bh4[2], bh4[3]);
                mma16816(sacc[2 * g],     qfh[ks], bl4[0], bl4[1]);
                mma16816(sacc[2 * g + 1], qfh[ks], bl4[2], bl4[3]);
                mma16816(sacc[2 * g],     qfl[ks], bh4[0], bh4[1]);
                mma16816(sacc[2 * g + 1], qfl[ks], bh4[2], bh4[3]);
            }
        }
#pragma unroll
        for (int j = 0; j < 8; j++)
#pragma unroll
            for (int t = 0; t < 4; t++) sacc[j][t] *= 0.125f;
        if (kvt == qt) {
            int cb = kv0 + 2 * (lane & 3);
#pragma unroll
            for (int j = 0; j < 8; j++) {
                int kc = cb + 8 * j;
                if (kc     > q0)     sacc[j][0] = -INFINITY;
                if (kc + 1 > q0)     sacc[j][1] = -INFINITY;
                if (kc     > q0 + 8) sacc[j][2] = -INFINITY;
                if (kc + 1 > q0 + 8) sacc[j][3] = -INFINITY;
            }
        }
        float mx0 = -INFINITY, mx1 = -INFINITY;
#pragma unroll
        for (int j = 0; j < 8; j++) {
            mx0 = fmaxf(mx0, fmaxf(sacc[j][0], sacc[j][1]));
            mx1 = fmaxf(mx1, fmaxf(sacc[j][2], sacc[j][3]));
        }
        mx0 = fmaxf(mx0, __shfl_xor_sync(0xffffffffu, mx0, 1));
        mx0 = fmaxf(mx0, __shfl_xor_sync(0xffffffffu, mx0, 2));
        mx1 = fmaxf(mx1, __shfl_xor_sync(0xffffffffu, mx1, 1));
        mx1 = fmaxf(mx1, __shfl_xor_sync(0xffffffffu, mx1, 2));
        float mn0 = fmaxf(m0, mx0), mn1 = fmaxf(m1, mx1);
        float cr0 = __expf(m0 - mn0), cr1 = __expf(m1 - mn1);
        l0 *= cr0; l1 *= cr1;
#pragma unroll
        for (int j = 0; j < 8; j++) {
            oacc[j][0] *= cr0; oacc[j][1] *= cr0;
            oacc[j][2] *= cr1; oacc[j][3] *= cr1;
        }
        uint32_t pf[4][4];
#pragma unroll
        for (int j = 0; j < 8; j++) {
            float p0 = __expf(sacc[j][0] - mn0);
            float p1 = __expf(sacc[j][1] - mn0);
            float p2 = __expf(sacc[j][2] - mn1);
            float p3 = __expf(sacc[j][3] - mn1);
            l0 += p0 + p1; l1 += p2 + p3;
            pf[j >> 1][(j & 1) * 2]     = packbf(p0, p1);
            pf[j >> 1][(j & 1) * 2 + 1] = packbf(p2, p3);
        }
        m0 = mn0; m1 = mn1;
#pragma unroll
        for (int kt = 0; kt < 4; kt++) {
            uint32_t va = sb + SVH + (kt * 16 + (lane & 15)) * AP
                        + ((lane >> 4) * 8) * 2;
#pragma unroll
            for (int gn = 0; gn < 4; gn++) {
                uint32_t vb[4];
                ldm4t(vb, va + gn * 32);
                mma16816(oacc[2 * gn],     pf[kt], vb[0], vb[1]);
                mma16816(oacc[2 * gn + 1], pf[kt], vb[2], vb[3]);
                ldm4t(vb, va + gn * 32 + (SVL - SVH));
                mma16816(oacc[2 * gn],     pf[kt], vb[0], vb[1]);
                mma16816(oacc[2 * gn + 1], pf[kt], vb[2], vb[3]);
            }
        }
    }

    l0 += __shfl_xor_sync(0xffffffffu, l0, 1);
    l0 += __shfl_xor_sync(0xffffffffu, l0, 2);
    l1 += __shfl_xor_sync(0xffffffffu, l1, 1);
    l1 += __shfl_xor_sync(0xffffffffu, l1, 2);
    float i0 = 1.f / l0, i1 = 1.f / l1;

    // epilogue: write bf16 hi/lo split at [m, h*64+dk] (K-major A for w_o GEMM)
    size_t r0 = (size_t)(b * S_ + q0) * D_ + h * DK_;
    size_t r1 = (size_t)(b * S_ + q0 + 8) * D_ + h * DK_;
#pragma unroll
    for (int j = 0; j < 8; j++) {
        int dk0 = 8 * j + 2 * (lane & 3);
        float a0 = oacc[j][0] * i0, a1 = oacc[j][1] * i0;
        float b0 = oacc[j][2] * i1, b1 = oacc[j][3] * i1;
        float h0, lo0, h1, lo1, h2, lo2, h3, lo3;
        split1(a0, h0, lo0); split1(a1, h1, lo1);
        split1(b0, h2, lo2); split1(b1, h3, lo3);
        *(uint32_t*)(oh + r0 + dk0) = packbf(h0, h1);
        *(uint32_t*)(ol + r0 + dk0) = packbf(lo0, lo1);
        *(uint32_t*)(oh + r1 + dk0) = packbf(h2, h3);
        *(uint32_t*)(ol + r1 + dk0) = packbf(lo2, lo3);
    }
}

// ---------------------------------------------------------------------------
// SwiGLU fused with split: reads combined [m, u|g] (8192 wide), writes hi/lo
// ---------------------------------------------------------------------------
__global__ void swiglu_split_kernel(const float* __restrict__ ug,
                                    __nv_bfloat16* __restrict__ hi,
                                    __nv_bfloat16* __restrict__ lo) {
    int i = blockIdx.x * blockDim.x + threadIdx.x;   // float4 units of output
    if (i >= M_ * DFF_ / 4) return;
    int m = i >> 10;          // /1024 float4 per row
    int f = i & 1023;
    const float4* row = (const float4*)(ug + (size_t)m * 8192);
    float4 uv = row[f];
    float4 gv = row[f + 1024];
    float4 r;
    r.x = uv.x * (1.0f / (1.0f + expf(-uv.x))) * gv.x;
    r.y = uv.y * (1.0f / (1.0f + expf(-uv.y))) * gv.y;
    r.z = uv.z * (1.0f / (1.0f + expf(-uv.z))) * gv.z;
    r.w = uv.w * (1.0f / (1.0f + expf(-uv.w))) * gv.w;
    uint2 uh, ul;
    split4_pack(r, uh, ul);
    ((uint2*)hi)[i] = uh;
    ((uint2*)lo)[i] = ul;
}

// ---------------------------------------------------------------------------
// Launch
// ---------------------------------------------------------------------------
extern "C" void kernel_launch(void* const* d_in, const int* in_sizes, int n_in,
                              void* d_out, int out_size) {
    const float* x   = (const float*)d_in[0];
    const float* w_q = (const float*)d_in[1];
    const float* w_k = (const float*)d_in[2];
    const float* w_v = (const float*)d_in[3];
    const float* w_o = (const float*)d_in[4];
    const float* ln1 = (const float*)d_in[5];
    const float* ln2 = (const float*)d_in[6];
    const float* w1  = (const float*)d_in[7];
    const float* w2  = (const float*)d_in[8];
    const float* w3  = (const float*)d_in[9];
    float* out = (float*)d_out;

    float *ffn, *x2;
    float2* rope;
    __nv_bfloat16 *sh, *sl, *wh, *wl;
    cudaGetSymbolAddress((void**)&ffn,  g_ffn);
    cudaGetSymbolAddress((void**)&x2,   g_x2);
    cudaGetSymbolAddress((void**)&rope, g_rope);
    cudaGetSymbolAddress((void**)&sh,   g_sh);
    cudaGetSymbolAddress((void**)&sl,   g_sl);
    cudaGetSymbolAddress((void**)&wh,   g_wh);
    cudaGetSymbolAddress((void**)&wl,   g_wl);

    cudaFuncSetAttribute(mma_gemm_kernel,
                         cudaFuncAttributeMaxDynamicSharedMemorySize, MG_SMEM);
    cudaFuncSetAttribute(attn_mma_kernel,
                         cudaFuncAttributeMaxDynamicSharedMemorySize, AT_SMEM);

    // 0) RoPE table + weight splits (MLP=4)
    rope_table_kernel<<<(S_ * 32 + 255) / 256, 256>>>(rope);
    wsplit_kernel<<<256, 256>>>(w_q, wh + OW_Q, wl + OW_Q, 262144);
    wsplit_kernel<<<256, 256>>>(w_k, wh + OW_K, wl + OW_K, 262144);
    wsplit_kernel<<<256, 256>>>(w_v, wh + OW_V, wl + OW_V, 262144);
    wsplit_kernel<<<256, 256>>>(w_o, wh + OW_O, wl + OW_O, 262144);
    wsplit_kernel<<<1024, 256>>>(w1, wh + OW_1, wl + OW_1, 1048576);
    wsplit_kernel<<<1024, 256>>>(w3, wh + OW_3, wl + OW_3, 1048576);
    wsplit_kernel<<<1024, 256>>>(w2, wh + OW_2, wl + OW_2, 1048576);

    // 1) h = rmsnorm(x, ln1) -> split directly
    rmsnorm_split_kernel<<<M_, 256>>>(x, ln1, sh, sl);

    // 2) qkv = h @ [wq|wk|wv]^T  (single N=3072 GEMM into g_ffn)
    mma_gemm_kernel<<<dim3(3072 / 128, M_ / 128), 256, MG_SMEM>>>(
        sh, sl, wh + OW_Q, wl + OW_Q, nullptr, ffn, M_, 3072, D_);

    // 3) RoPE + split + repack (overwrites h split region)
    qkv_prep_kernel<<<(M_ * D_ / 2 + 255) / 256, 256>>>(ffn, rope, sh, sl);

    // 4) attention -> bf16 split at OA_
    attn_mma_kernel<<<dim3(S_ / 64, H_, B_), 128, AT_SMEM>>>(sh, sl, sh + OA_, sl + OA_);

    // 5) x2 = x + attn @ w_o^T
    mma_gemm_kernel<<<dim3(D_ / 128, M_ / 128), 256, MG_SMEM>>>(
        sh + OA_, sl + OA_, wh + OW_O, wl + OW_O, x, x2, M_, D_, D_);

    // 6) h2 = rmsnorm(x2, ln2) -> split
    rmsnorm_split_kernel<<<M_, 256>>>(x2, ln2, sh, sl);

    // 7) [u|g] = h2 @ [w1|w3]^T  (single N=8192 GEMM into g_ffn)
    mma_gemm_kernel<<<dim3(8192 / 128, M_ / 128), 256, MG_SMEM>>>(
        sh, sl, wh + OW_1, wl + OW_1, nullptr, ffn, M_, 8192, D_);

    // 8) swiglu + split
    swiglu_split_kernel<<<(M_ * DFF_ / 4 + 255) / 256, 256>>>(ffn, sh, sl);

    // 9) out = x2 + silu @ w2^T  (K = 4096)
    mma_gemm_kernel<<<dim3(D_ / 128, M_ / 128), 256, MG_SMEM>>>(
        sh, sl, wh + OW_2, wl + OW_2, x2, out, M_, D_, DFF_);
}